// round 5
// baseline (speedup 1.0000x reference)
#include <cuda_runtime.h>
#include <math.h>
#include <stdint.h>

// FCOS post-process, GB300 (sm_103a), round 5: 5-kernel pipeline.
// K1 sample(+t14 by last block)  K2 compact(xmin inline, 80-class stripes)
// K3 refine(verify->sort->decode)  K4 fallback(exact, flag-guarded, inline refine)
// K5 mask+NMS fused (smem suppression matrix) + output.
// All per-call state self-cleaned by its consumer (globals start zeroed).

#define NIMG 8
#define NCLS 80
#define PP   15200
#define CPE  (NCLS*PP)        // 1216000
#define TOPK 1000
#define KPAD 1024
#define CAP  262144
#define CAP2 2048
#define NSAMP 960             // 60 runs x 16 consecutive points
#define NITEM (NSAMP*10)      // x 10 class-blocks of 8
#define SBLK 38               // sample blocks per image
#define TARGET_S 100
#define C0 (-2.9444389791664403f)   // logit(0.05)
typedef unsigned long long ull;
typedef unsigned int uint;

// ---------------- device scratch (module-load zeroed; consumers re-zero) -----
__device__ ull  g_cand[NIMG][CAP];                   // 16 MB
__device__ uint g_hist14[NIMG][4096];
__device__ uint g_candcnt[NIMG];
__device__ uint g_scount[NIMG];
__device__ uint g_T[NIMG];
__device__ float g_edgef[NIMG];
__device__ uint g_flag[NIMG];
__device__ float g_box [NIMG][KPAD][4];
__device__ float g_obox[NIMG][KPAD][4];
__device__ float g_area[NIMG][KPAD];
__device__ float g_lab [NIMG][KPAD];
__device__ float g_sc  [NIMG][KPAD];
__device__ uint g_validbits[NIMG][32];

__device__ __forceinline__ float sig_exact(float v) {
    return 1.0f / (1.0f + expf(-v));
}
__device__ __forceinline__ float score_apx(float x, float eyp) {
    return __frcp_rn(__fmul_rn(__fadd_rn(1.0f, __expf(-x)), eyp));
}

// ---------------- K1: coalesced sampled hist + t14 by last block -------------
__global__ __launch_bounds__(256) void k_sample(const float* __restrict__ cls,
                                                const float* __restrict__ ctr) {
    int n = blockIdx.y;
    int t = threadIdx.x;
    int item = blockIdx.x * 256 + t;
    if (item < NITEM) {
        int k  = item % NSAMP;
        int cb = item / NSAMP;
        int p = (k >> 4) * 253 + (k & 15);           // 60 runs of 16 points
        float eyp = __fadd_rn(1.0f, __expf(-ctr[(size_t)n * PP + p]));
        const float* base = cls + (size_t)n * CPE + p + (size_t)cb * 8 * PP;
        float xs[8];
#pragma unroll
        for (int i = 0; i < 8; i++) xs[i] = base[(size_t)i * PP];
#pragma unroll
        for (int i = 0; i < 8; i++) {
            if (xs[i] > C0) {
                uint b14 = __float_as_uint(score_apx(xs[i], eyp)) >> 18;
                if (b14 > 4095u) b14 = 4095u;
                if (b14) atomicAdd(&g_hist14[n][b14], 1u);
            }
        }
    }
    __threadfence();
    __shared__ uint s_old;
    __shared__ uint ss[256];
    __syncthreads();
    if (t == 0) s_old = atomicAdd(&g_scount[n], 1u);
    __syncthreads();
    if (s_old != SBLK - 1) return;                   // only last block continues
    // ---- t14: suffix scan over 4096 bins, zero hist behind the reads ----
    uint loc[16]; uint s = 0;
#pragma unroll
    for (int i = 0; i < 16; i++) {
        loc[i] = __ldcg(&g_hist14[n][t * 16 + i]);
        g_hist14[n][t * 16 + i] = 0u;
        s += loc[i];
    }
    ss[t] = s;
    __syncthreads();
    for (int off = 1; off < 256; off <<= 1) {
        uint v = (t + off < 256) ? ss[t + off] : 0u;
        __syncthreads();
        ss[t] += v;
        __syncthreads();
    }
    uint mine = ss[t];
    uint above = (t + 1 < 256) ? ss[t + 1] : 0u;
    if (mine >= TARGET_S && above < TARGET_S) {
        uint cum = above, T = 1;
        for (int i = 15; i >= 0; i--) {
            cum += loc[i];
            if (cum >= TARGET_S) { T = (uint)(t * 16 + i); break; }
        }
        if (T < 1) T = 1;
        uint gate = (T > 2) ? T - 1 : 1u;
        g_T[n] = T;
        g_edgef[n] = __uint_as_float(gate << 18);
    }
    if (t == 0) {
        if (ss[0] < TARGET_S) {                      // degenerate: keep all
            g_T[n] = 1;
            g_edgef[n] = __uint_as_float(1u << 18);
        }
        g_scount[n] = 0u;                            // restore for next call
    }
}

// ---------------- K2: full scan, xmin inline, 20-class stripes ---------------
// grid (15, 4, NIMG): thread owns 4 points (float4) x 20 classes.
__global__ __launch_bounds__(256) void k_compact(const float* __restrict__ cls,
                                                 const float* __restrict__ ctr) {
    int n = blockIdx.z;
    int q = blockIdx.x * 256 + threadIdx.x;
    if (q >= PP / 4) return;
    int pb = q * 4;
    float edge = g_edgef[n];
    float4 y4 = *(const float4*)(ctr + (size_t)n * PP + pb);
    float yv[4] = {y4.x, y4.y, y4.z, y4.w};
    float xm[4];
#pragma unroll
    for (int j = 0; j < 4; j++) {
        float eyp = __fadd_rn(1.0f, __expf(-yv[j]));
        float K = __fdividef(1.0f, __fmul_rn(edge, eyp)) - 1.0f;
        xm[j] = (K > 0.0f) ? (-__logf(K) - 0.002f) : 3.0e38f;
    }
    int c0 = blockIdx.y * 20;
    const float* base = cls + (size_t)n * CPE + pb;
#pragma unroll
    for (int cb = 0; cb < 5; cb++) {
        float4 xv[4];
#pragma unroll
        for (int i = 0; i < 4; i++)
            xv[i] = *(const float4*)(base + (size_t)(c0 + cb * 4 + i) * PP);
#pragma unroll
        for (int i = 0; i < 4; i++) {
            float xs[4] = {xv[i].x, xv[i].y, xv[i].z, xv[i].w};
            int c = c0 + cb * 4 + i;
#pragma unroll
            for (int j = 0; j < 4; j++) {
                float x = xs[j];
                if (x > C0 && x >= xm[j]) {          // rare (~2.5K/image)
                    float ss = sig_exact(x);
                    if (ss > 0.05f) {
                        float score = __fmul_rn(ss, sig_exact(yv[j]));
                        uint sb = __float_as_uint(score);
                        uint idx = (uint)((pb + j) * NCLS + c);
                        ull key = ((ull)sb << 32) | (ull)(0xFFFFFFFFu - idx);
                        uint am = __activemask();
                        int lane = threadIdx.x & 31;
                        int lr = __ffs(am) - 1;
                        uint basep = 0;
                        if (lane == lr)
                            basep = atomicAdd(&g_candcnt[n], (uint)__popc(am));
                        basep = __shfl_sync(am, basep, lr);
                        uint pos = basep + __popc(am & ((1u << lane) - 1u));
                        if (pos < CAP) g_cand[n][pos] = key;
                    }
                }
            }
        }
    }
}

// ---------------- shared refine core: (direct|radix) + bitonic + decode ------
__device__ void refine_core(int n, uint M,
                            const float* __restrict__ loc,
                            const float* __restrict__ reg,
                            const float* __restrict__ info,
                            ull* slist, uint* shist, uint* smisc) {
    int t = threadIdx.x;
    if (M <= CAP2) {
        for (int q = t; q < CAP2; q += 1024)
            slist[q] = (q < (int)M) ? g_cand[n][q] : 0ull;
        __syncthreads();
    } else {
        if (t == 0) { smisc[0] = 0u; smisc[1] = TOPK; smisc[2] = 0u; }
        __syncthreads();
        for (int lvl = 3; lvl >= 0; lvl--) {
            if (t < 256) shist[t] = 0u;
            __syncthreads();
            uint pfx = smisc[0];
            for (uint idx = t; idx < M; idx += 1024) {
                uint bits = (uint)(g_cand[n][idx] >> 32);
                bool cond = (lvl == 3) || ((bits >> ((lvl + 1) * 8)) == pfx);
                if (cond) atomicAdd(&shist[(bits >> (lvl * 8)) & 255u], 1u);
            }
            __syncthreads();
            if (t == 0) {
                uint cum = 0, rr = smisc[1]; int chosen = 0;
                for (int b = 255; b >= 0; b--) {
                    cum += shist[b];
                    if (cum >= rr) { chosen = b; smisc[1] = rr - (cum - shist[b]); break; }
                }
                smisc[0] = (smisc[0] << 8) | (uint)chosen;
            }
            __syncthreads();
        }
        uint sstar = smisc[0];
        for (int q = t; q < CAP2; q += 1024) slist[q] = 0ull;
        __syncthreads();
        for (uint idx = t; idx < M; idx += 1024) {
            ull key = g_cand[n][idx];
            if ((uint)(key >> 32) >= sstar) {
                uint pos = atomicAdd(&smisc[2], 1u);
                if (pos < CAP2) slist[pos] = key;
            }
        }
        __syncthreads();
    }
    for (int k2 = 2; k2 <= CAP2; k2 <<= 1) {
        for (int s2 = k2 >> 1; s2 >= 1; s2 >>= 1) {
            int i = ((t & ~(s2 - 1)) << 1) | (t & (s2 - 1));
            int l = i | s2;
            ull a = slist[i], b = slist[l];
            bool dir = ((i & k2) == 0);
            if ((a < b) == dir) { slist[i] = b; slist[l] = a; }
            __syncthreads();
        }
    }
    // decode (t = rank)
    float x1 = 0, y1 = 0, x2 = 0, y2 = 0, labf = 0, score = 0;
    float ox1 = 0, oy1 = 0, ox2 = 0, oy2 = 0, area = 0;
    bool valid = false;
    if (t < TOPK) {
        ull key = slist[t];
        uint sb = (uint)(key >> 32);
        if (sb) {
            score = __uint_as_float(sb);
            uint i = 0xFFFFFFFFu - (uint)(key & 0xFFFFFFFFull);
            int p = (int)(i / NCLS);
            int c = (int)(i - (uint)(p * NCLS));
            labf = (float)(c + 1);
            float lx = loc[2 * p], ly = loc[2 * p + 1];
            float rl = reg[((size_t)(n * 4 + 0)) * PP + p];
            float rt = reg[((size_t)(n * 4 + 1)) * PP + p];
            float rr = reg[((size_t)(n * 4 + 2)) * PP + p];
            float rb = reg[((size_t)(n * 4 + 3)) * PP + p];
            float hm1 = __fsub_rn(info[2 * n + 0], 1.0f);
            float wm1 = __fsub_rn(info[2 * n + 1], 1.0f);
            x1 = fminf(fmaxf(__fsub_rn(lx, rl), 0.0f), wm1);
            y1 = fminf(fmaxf(__fsub_rn(ly, rt), 0.0f), hm1);
            x2 = fminf(fmaxf(__fadd_rn(lx, rr), 0.0f), wm1);
            y2 = fminf(fmaxf(__fadd_rn(ly, rb), 0.0f), hm1);
            valid = (score > 0.0f) &&
                    (__fsub_rn(x2, x1) >= 0.0f) && (__fsub_rn(y2, y1) >= 0.0f);
            float off = __fmul_rn(labf, 1.0e5f);
            ox1 = __fadd_rn(x1, off); oy1 = __fadd_rn(y1, off);
            ox2 = __fadd_rn(x2, off); oy2 = __fadd_rn(y2, off);
            area = __fmul_rn(fmaxf(__fsub_rn(ox2, ox1), 0.0f),
                             fmaxf(__fsub_rn(oy2, oy1), 0.0f));
        }
    }
    g_box[n][t][0] = x1; g_box[n][t][1] = y1; g_box[n][t][2] = x2; g_box[n][t][3] = y2;
    g_obox[n][t][0] = ox1; g_obox[n][t][1] = oy1; g_obox[n][t][2] = ox2; g_obox[n][t][3] = oy2;
    g_area[n][t] = area; g_lab[n][t] = labf; g_sc[n][t] = score;
    uint bal = __ballot_sync(0xffffffffu, valid);
    if ((t & 31) == 0) g_validbits[n][t >> 5] = bal;
}

// ---------------- K3: verify + refine ----------------------------------------
__global__ __launch_bounds__(1024) void k_refine(const float* __restrict__ loc,
                                                 const float* __restrict__ reg,
                                                 const float* __restrict__ info) {
    __shared__ ull slist[CAP2];
    __shared__ uint shist[256];
    __shared__ uint smisc[4];
    int n = blockIdx.x;
    int t = threadIdx.x;
    uint attempted = g_candcnt[n];
    uint M = attempted > CAP ? CAP : attempted;
    if (t == 0) smisc[3] = 0u;
    __syncthreads();
    uint Vb = g_T[n] << 18;
    uint local = 0;
    for (uint idx = t; idx < M; idx += 1024)
        if ((uint)(g_cand[n][idx] >> 32) >= Vb) local++;
    if (local) atomicAdd(&smisc[3], local);
    __syncthreads();
    if (smisc[3] < TOPK || attempted > CAP) {        // not provably complete
        if (t == 0) g_flag[n] = 1u;
        return;                                      // fallback rebuilds
    }
    refine_core(n, M, loc, reg, info, slist, shist, smisc);
    if (t == 0) g_candcnt[n] = 0u;                   // restore for next call
}

// ---------------- K4: exact fallback (flag-guarded; never in practice) -------
__global__ __launch_bounds__(1024) void k_fallback(const float* __restrict__ cls,
                                                   const float* __restrict__ ctr,
                                                   const float* __restrict__ loc,
                                                   const float* __restrict__ reg,
                                                   const float* __restrict__ info) {
    int n = blockIdx.x;
    if (!g_flag[n]) return;
    __shared__ ull slist[CAP2];
    __shared__ uint shist[256];
    __shared__ uint smisc[4];
    __shared__ uint h8[256];
    __shared__ uint s_b1;
    int t = threadIdx.x;
    if (t < 256) h8[t] = 0u;
    if (t == 0) g_candcnt[n] = 0u;
    __syncthreads();
    const float* clsn = cls + (size_t)n * CPE;
    const float* ctrn = ctr + (size_t)n * PP;
    for (int j = t; j < CPE; j += 1024) {
        int p = j % PP;
        float s = sig_exact(clsn[j]);
        if (s > 0.05f) {
            uint b = __float_as_uint(__fmul_rn(s, sig_exact(ctrn[p]))) >> 24;
            if (b) atomicAdd(&h8[b], 1u);
        }
    }
    __syncthreads();
    if (t == 0) {
        uint cum = 0, b1 = 1;
        for (int b = 255; b >= 1; b--) {
            cum += h8[b];
            if (cum >= TOPK) { b1 = (uint)b; break; }
        }
        s_b1 = b1;
    }
    __syncthreads();
    uint b1 = s_b1;
    for (int j = t; j < CPE; j += 1024) {
        int p = j % PP;
        float s = sig_exact(clsn[j]);
        if (s > 0.05f) {
            float score = __fmul_rn(s, sig_exact(ctrn[p]));
            uint sb = __float_as_uint(score);
            if ((sb >> 24) >= b1) {
                int c = j / PP;
                uint i = (uint)(p * NCLS + c);
                ull key = ((ull)sb << 32) | (ull)(0xFFFFFFFFu - i);
                uint pos = atomicAdd(&g_candcnt[n], 1u);
                if (pos < CAP) g_cand[n][pos] = key;
            }
        }
    }
    __syncthreads();
    uint attempted = g_candcnt[n];
    uint M = attempted > CAP ? CAP : attempted;
    refine_core(n, M, loc, reg, info, slist, shist, smisc);
    if (t == 0) { g_flag[n] = 0u; g_candcnt[n] = 0u; }
}

// ---------------- K5: fused mask (into smem) + greedy NMS + output -----------
__global__ __launch_bounds__(1024, 1) void k_masknms(float* __restrict__ out) {
    extern __shared__ uint smask[];                  // 1024 x 32 words = 128 KB
    __shared__ float4 sob[KPAD];
    __shared__ float  sar[KPAD];
    __shared__ float  slb[KPAD];
    int n = blockIdx.x;
    int t = threadIdx.x;
    if (t < 600) out[(size_t)n * 600 + t] = 0.0f;
    sob[t] = *(const float4*)&g_obox[n][t][0];
    sar[t] = g_area[n][t];
    slb[t] = g_lab[n][t];
    __syncthreads();
    int warp = t >> 5, lane = t & 31;
    for (int r = 0; r < 32; r++) {
        int i = r * 32 + warp;                       // w0 = i>>5 = r (balanced)
        float4 bi = sob[i];
        float ai = sar[i];
        float li = slb[i];
        uint myword = 0u;
        for (int w = r; w < 32; w++) {
            int j = w * 32 + lane;
            bool lm = (j > i) && (slb[j] == li);     // cross-class IoU exactly 0
            bool sup = false;
            if (__ballot_sync(0xffffffffu, lm)) {
                if (lm) {
                    float4 bj = sob[j];
                    float wv = fmaxf(__fsub_rn(fminf(bi.z, bj.z), fmaxf(bi.x, bj.x)), 0.0f);
                    float hv = fmaxf(__fsub_rn(fminf(bi.w, bj.w), fmaxf(bi.y, bj.y)), 0.0f);
                    float inter = __fmul_rn(wv, hv);
                    float denom = __fadd_rn(__fsub_rn(__fadd_rn(ai, sar[j]), inter), 1e-9f);
                    sup = inter > __fmul_rn(0.6f, denom);   // iou > 0.6
                }
            }
            uint bits = __ballot_sync(0xffffffffu, sup);
            if (lane == w) myword = bits;
        }
        smask[i * 32 + lane] = (lane >= r) ? myword : 0u;
    }
    __syncthreads();
    if (t < 32) {
        unsigned validw = g_validbits[n][lane];
        unsigned removew = 0u;
        for (int g = 0; g < 32; g++) {
            unsigned cur_sup = __shfl_sync(0xffffffffu, removew, g);
            unsigned cur_val = __shfl_sync(0xffffffffu, validw, g);
            unsigned rowv[32], diag[32];
#pragma unroll
            for (int b = 0; b < 32; b++) {
                rowv[b] = smask[(g * 32 + b) * 32 + lane];
                diag[b] = smask[(g * 32 + b) * 32 + g];
            }
#pragma unroll
            for (int b = 0; b < 32; b++) {
                bool alive = ((cur_val >> b) & 1u) && !((cur_sup >> b) & 1u);
                if (alive) { removew |= rowv[b]; cur_sup |= diag[b]; }
            }
        }
        unsigned keepw = validw & ~removew;
        int cnt = __popc(keepw);
        int inc = cnt;
        for (int o = 1; o < 32; o <<= 1) {
            int v = __shfl_up_sync(0xffffffffu, inc, o);
            if (lane >= o) inc += v;
        }
        int basei = inc - cnt;
        unsigned m = keepw;
        while (m) {
            int b = __ffs(m) - 1;
            m &= m - 1;
            int rank = basei + __popc(keepw & ((1u << b) - 1u));
            if (rank < 100) {
                int i = lane * 32 + b;
                float* o6 = out + ((size_t)n * 100 + rank) * 6;
                o6[0] = g_box[n][i][0]; o6[1] = g_box[n][i][1];
                o6[2] = g_box[n][i][2]; o6[3] = g_box[n][i][3];
                o6[4] = g_lab[n][i];    o6[5] = g_sc[n][i];
            }
        }
    }
}

// ---------------- launch -----------------------------------------------------
extern "C" void kernel_launch(void* const* d_in, const int* in_sizes, int n_in,
                              void* d_out, int out_size) {
    const float* loc  = (const float*)d_in[0];
    const float* cls  = (const float*)d_in[1];
    const float* reg  = (const float*)d_in[2];
    const float* ctr  = (const float*)d_in[3];
    const float* info = (const float*)d_in[4];
    float* out = (float*)d_out;
    (void)in_sizes; (void)n_in; (void)out_size;

    cudaFuncSetAttribute(k_masknms, cudaFuncAttributeMaxDynamicSharedMemorySize,
                         KPAD * 32 * 4);

    k_sample<<<dim3(SBLK, NIMG), 256>>>(cls, ctr);
    k_compact<<<dim3(15, 4, NIMG), 256>>>(cls, ctr);
    k_refine<<<NIMG, 1024>>>(loc, reg, info);
    k_fallback<<<NIMG, 1024>>>(cls, ctr, loc, reg, info);
    k_masknms<<<NIMG, 1024, KPAD * 32 * 4>>>(out);
}

// round 6
// speedup vs baseline: 1.0505x; 1.0505x over previous
#include <cuda_runtime.h>
#include <math.h>
#include <stdint.h>

// FCOS post-process, GB300 (sm_103a), round 6: 6 kernels.
// K1 sample (+t14 +xmin table by last block/image)
// K2 compact: pure compare-gated 39MB scan, exact rescoring of rare passers
// K3 refine: verify -> sort top-1000 -> decode     K4 fallback (guarded, no-op)
// K5 mask: 64 blocks suppression matrix            K6 nms: serial greedy + out

#define NIMG 8
#define NCLS 80
#define PP   15200
#define CPE  (NCLS*PP)        // 1216000
#define TOPK 1000
#define KPAD 1024
#define CAP  262144
#define CAP2 2048
#define NSAMP 960             // 60 runs x 16 consecutive points
#define NITEM (NSAMP*10)
#define SBLK 38
#define TARGET_S 100
#define C0 (-2.9444389791664403f)   // logit(0.05)
typedef unsigned long long ull;
typedef unsigned int uint;

// ---------------- device scratch (module-load zeroed; self-cleaning) ---------
__device__ ull  g_cand[NIMG][CAP];                   // 16 MB
__device__ uint g_hist14[NIMG][4096];
__device__ uint g_candcnt[NIMG];
__device__ uint g_scount[NIMG];
__device__ uint g_T[NIMG];
__device__ uint g_flag[NIMG];
__device__ float g_xmin[NIMG][PP];
__device__ float g_box [NIMG][KPAD][4];
__device__ float g_obox[NIMG][KPAD][4];
__device__ float g_area[NIMG][KPAD];
__device__ float g_lab [NIMG][KPAD];
__device__ float g_sc  [NIMG][KPAD];
__device__ uint g_validbits[NIMG][32];
__device__ uint g_mask[NIMG][KPAD][32];              // 1 MB

__device__ __forceinline__ float sig_exact(float v) {
    return 1.0f / (1.0f + expf(-v));
}
__device__ __forceinline__ float score_apx(float x, float eyp) {
    return __frcp_rn(__fmul_rn(__fadd_rn(1.0f, __expf(-x)), eyp));
}

// ---------------- K1: sampled hist; last block: t14 + xmin table -------------
__global__ __launch_bounds__(256) void k_sample(const float* __restrict__ cls,
                                                const float* __restrict__ ctr) {
    __shared__ uint s_old;
    __shared__ uint ss[256];
    __shared__ float s_edge;
    int n = blockIdx.y;
    int t = threadIdx.x;
    int item = blockIdx.x * 256 + t;
    if (item < NITEM) {
        int k  = item % NSAMP;
        int cb = item / NSAMP;
        int p = (k >> 4) * 253 + (k & 15);           // 60 runs of 16 points
        float eyp = __fadd_rn(1.0f, __expf(-ctr[(size_t)n * PP + p]));
        const float* base = cls + (size_t)n * CPE + p + (size_t)cb * 8 * PP;
        float xs[8];
#pragma unroll
        for (int i = 0; i < 8; i++) xs[i] = base[(size_t)i * PP];
#pragma unroll
        for (int i = 0; i < 8; i++) {
            if (xs[i] > C0) {
                uint b14 = __float_as_uint(score_apx(xs[i], eyp)) >> 18;
                if (b14 > 4095u) b14 = 4095u;
                if (b14) atomicAdd(&g_hist14[n][b14], 1u);
            }
        }
    }
    __threadfence();
    __syncthreads();
    if (t == 0) s_old = atomicAdd(&g_scount[n], 1u);
    __syncthreads();
    if (s_old != SBLK - 1) return;                   // only last block continues
    // ---- t14: suffix scan over 4096 bins; zero hist behind the reads ----
    uint loc[16]; uint s = 0;
#pragma unroll
    for (int i = 0; i < 16; i++) {
        loc[i] = __ldcg(&g_hist14[n][t * 16 + i]);
        g_hist14[n][t * 16 + i] = 0u;
        s += loc[i];
    }
    ss[t] = s;
    __syncthreads();
    for (int off = 1; off < 256; off <<= 1) {
        uint v = (t + off < 256) ? ss[t + off] : 0u;
        __syncthreads();
        ss[t] += v;
        __syncthreads();
    }
    uint mine = ss[t];
    uint above = (t + 1 < 256) ? ss[t + 1] : 0u;
    if (mine >= TARGET_S && above < TARGET_S) {
        uint cum = above, T = 1;
        for (int i = 15; i >= 0; i--) {
            cum += loc[i];
            if (cum >= TARGET_S) { T = (uint)(t * 16 + i); break; }
        }
        if (T < 1) T = 1;
        uint gate = (T > 2) ? T - 1 : 1u;
        g_T[n] = T;
        s_edge = __uint_as_float(gate << 18);
    }
    if (t == 0) {
        g_scount[n] = 0u;                            // restore for next call
        if (ss[0] < TARGET_S) {                      // degenerate: keep all
            g_T[n] = 1;
            s_edge = __uint_as_float(1u << 18);
        }
    }
    __syncthreads();
    // ---- xmin table for all points of this image ----
    float edge = s_edge;
    for (int p = t; p < PP; p += 256) {
        float eyp = __fadd_rn(1.0f, __expf(-ctr[(size_t)n * PP + p]));
        float K = __fdividef(1.0f, __fmul_rn(edge, eyp)) - 1.0f;
        float xm = (K > 0.0f) ? (-__logf(K) - 0.002f) : 3.0e38f;
        g_xmin[n][p] = fmaxf(xm, C0);                // bake candidacy bound in
    }
}

// ---------------- K2: pure compare-gated full scan ---------------------------
// grid (15, 10, NIMG): thread owns 4 points (float4) x 8 classes, MLP 8.
__global__ __launch_bounds__(256) void k_compact(const float* __restrict__ cls,
                                                 const float* __restrict__ ctr) {
    int n = blockIdx.z;
    int q = blockIdx.x * 256 + threadIdx.x;
    if (q >= PP / 4) return;
    int pb = q * 4;
    float4 xm4 = *(const float4*)&g_xmin[n][pb];
    float xm[4] = {xm4.x, xm4.y, xm4.z, xm4.w};
    int c0 = blockIdx.y * 8;
    const float* base = cls + (size_t)n * CPE + pb;
    float4 xv[8];
#pragma unroll
    for (int i = 0; i < 8; i++)
        xv[i] = *(const float4*)(base + (size_t)(c0 + i) * PP);
#pragma unroll
    for (int i = 0; i < 8; i++) {
        float xs[4] = {xv[i].x, xv[i].y, xv[i].z, xv[i].w};
        int c = c0 + i;
#pragma unroll
        for (int j = 0; j < 4; j++) {
            float x = xs[j];
            if (x >= xm[j]) {                        // rare (~2.5K/image)
                float s = sig_exact(x);
                if (s > 0.05f) {                     // exact candidacy
                    float y = ctr[(size_t)n * PP + pb + j];
                    float score = __fmul_rn(s, sig_exact(y));
                    uint sb = __float_as_uint(score);
                    uint idx = (uint)((pb + j) * NCLS + c);
                    ull key = ((ull)sb << 32) | (ull)(0xFFFFFFFFu - idx);
                    uint am = __activemask();
                    int lane = threadIdx.x & 31;
                    int lr = __ffs(am) - 1;
                    uint basep = 0;
                    if (lane == lr)
                        basep = atomicAdd(&g_candcnt[n], (uint)__popc(am));
                    basep = __shfl_sync(am, basep, lr);
                    uint pos = basep + __popc(am & ((1u << lane) - 1u));
                    if (pos < CAP) g_cand[n][pos] = key;
                }
            }
        }
    }
}

// ---------------- shared refine core: (direct|radix) + bitonic + decode ------
__device__ void refine_core(int n, uint M,
                            const float* __restrict__ loc,
                            const float* __restrict__ reg,
                            const float* __restrict__ info,
                            ull* slist, uint* shist, uint* smisc) {
    int t = threadIdx.x;
    if (M <= CAP2) {
        for (int q = t; q < CAP2; q += 1024)
            slist[q] = (q < (int)M) ? g_cand[n][q] : 0ull;
        __syncthreads();
    } else {
        if (t == 0) { smisc[0] = 0u; smisc[1] = TOPK; smisc[2] = 0u; }
        __syncthreads();
        for (int lvl = 3; lvl >= 0; lvl--) {
            if (t < 256) shist[t] = 0u;
            __syncthreads();
            uint pfx = smisc[0];
            for (uint idx = t; idx < M; idx += 1024) {
                uint bits = (uint)(g_cand[n][idx] >> 32);
                bool cond = (lvl == 3) || ((bits >> ((lvl + 1) * 8)) == pfx);
                if (cond) atomicAdd(&shist[(bits >> (lvl * 8)) & 255u], 1u);
            }
            __syncthreads();
            if (t == 0) {
                uint cum = 0, rr = smisc[1]; int chosen = 0;
                for (int b = 255; b >= 0; b--) {
                    cum += shist[b];
                    if (cum >= rr) { chosen = b; smisc[1] = rr - (cum - shist[b]); break; }
                }
                smisc[0] = (smisc[0] << 8) | (uint)chosen;
            }
            __syncthreads();
        }
        uint sstar = smisc[0];
        for (int q = t; q < CAP2; q += 1024) slist[q] = 0ull;
        __syncthreads();
        for (uint idx = t; idx < M; idx += 1024) {
            ull key = g_cand[n][idx];
            if ((uint)(key >> 32) >= sstar) {
                uint pos = atomicAdd(&smisc[2], 1u);
                if (pos < CAP2) slist[pos] = key;
            }
        }
        __syncthreads();
    }
    for (int k2 = 2; k2 <= CAP2; k2 <<= 1) {
        for (int s2 = k2 >> 1; s2 >= 1; s2 >>= 1) {
            int i = ((t & ~(s2 - 1)) << 1) | (t & (s2 - 1));
            int l = i | s2;
            ull a = slist[i], b = slist[l];
            bool dir = ((i & k2) == 0);
            if ((a < b) == dir) { slist[i] = b; slist[l] = a; }
            __syncthreads();
        }
    }
    // decode (t = rank)
    float x1 = 0, y1 = 0, x2 = 0, y2 = 0, labf = 0, score = 0;
    float ox1 = 0, oy1 = 0, ox2 = 0, oy2 = 0, area = 0;
    bool valid = false;
    if (t < TOPK) {
        ull key = slist[t];
        uint sb = (uint)(key >> 32);
        if (sb) {
            score = __uint_as_float(sb);
            uint i = 0xFFFFFFFFu - (uint)(key & 0xFFFFFFFFull);
            int p = (int)(i / NCLS);
            int c = (int)(i - (uint)(p * NCLS));
            labf = (float)(c + 1);
            float lx = loc[2 * p], ly = loc[2 * p + 1];
            float rl = reg[((size_t)(n * 4 + 0)) * PP + p];
            float rt = reg[((size_t)(n * 4 + 1)) * PP + p];
            float rr = reg[((size_t)(n * 4 + 2)) * PP + p];
            float rb = reg[((size_t)(n * 4 + 3)) * PP + p];
            float hm1 = __fsub_rn(info[2 * n + 0], 1.0f);
            float wm1 = __fsub_rn(info[2 * n + 1], 1.0f);
            x1 = fminf(fmaxf(__fsub_rn(lx, rl), 0.0f), wm1);
            y1 = fminf(fmaxf(__fsub_rn(ly, rt), 0.0f), hm1);
            x2 = fminf(fmaxf(__fadd_rn(lx, rr), 0.0f), wm1);
            y2 = fminf(fmaxf(__fadd_rn(ly, rb), 0.0f), hm1);
            valid = (score > 0.0f) &&
                    (__fsub_rn(x2, x1) >= 0.0f) && (__fsub_rn(y2, y1) >= 0.0f);
            float off = __fmul_rn(labf, 1.0e5f);
            ox1 = __fadd_rn(x1, off); oy1 = __fadd_rn(y1, off);
            ox2 = __fadd_rn(x2, off); oy2 = __fadd_rn(y2, off);
            area = __fmul_rn(fmaxf(__fsub_rn(ox2, ox1), 0.0f),
                             fmaxf(__fsub_rn(oy2, oy1), 0.0f));
        }
    }
    g_box[n][t][0] = x1; g_box[n][t][1] = y1; g_box[n][t][2] = x2; g_box[n][t][3] = y2;
    g_obox[n][t][0] = ox1; g_obox[n][t][1] = oy1; g_obox[n][t][2] = ox2; g_obox[n][t][3] = oy2;
    g_area[n][t] = area; g_lab[n][t] = labf; g_sc[n][t] = score;
    uint bal = __ballot_sync(0xffffffffu, valid);
    if ((t & 31) == 0) g_validbits[n][t >> 5] = bal;
}

// ---------------- K3: verify + refine ----------------------------------------
__global__ __launch_bounds__(1024) void k_refine(const float* __restrict__ loc,
                                                 const float* __restrict__ reg,
                                                 const float* __restrict__ info) {
    __shared__ ull slist[CAP2];
    __shared__ uint shist[256];
    __shared__ uint smisc[4];
    int n = blockIdx.x;
    int t = threadIdx.x;
    uint attempted = g_candcnt[n];
    uint M = attempted > CAP ? CAP : attempted;
    if (t == 0) smisc[3] = 0u;
    __syncthreads();
    uint Vb = g_T[n] << 18;
    uint local = 0;
    for (uint idx = t; idx < M; idx += 1024)
        if ((uint)(g_cand[n][idx] >> 32) >= Vb) local++;
    if (local) atomicAdd(&smisc[3], local);
    __syncthreads();
    if (smisc[3] < TOPK || attempted > CAP) {        // not provably complete
        if (t == 0) g_flag[n] = 1u;
        return;                                      // fallback rebuilds
    }
    refine_core(n, M, loc, reg, info, slist, shist, smisc);
    if (t == 0) g_candcnt[n] = 0u;                   // restore for next call
}

// ---------------- K4: exact fallback (guarded; never in practice) ------------
__global__ __launch_bounds__(1024) void k_fallback(const float* __restrict__ cls,
                                                   const float* __restrict__ ctr,
                                                   const float* __restrict__ loc,
                                                   const float* __restrict__ reg,
                                                   const float* __restrict__ info) {
    int n = blockIdx.x;
    if (!g_flag[n]) return;
    __shared__ ull slist[CAP2];
    __shared__ uint shist[256];
    __shared__ uint smisc[4];
    __shared__ uint h8[256];
    __shared__ uint s_b1;
    int t = threadIdx.x;
    if (t < 256) h8[t] = 0u;
    if (t == 0) g_candcnt[n] = 0u;
    __syncthreads();
    const float* clsn = cls + (size_t)n * CPE;
    const float* ctrn = ctr + (size_t)n * PP;
    for (int j = t; j < CPE; j += 1024) {
        int p = j % PP;
        float s = sig_exact(clsn[j]);
        if (s > 0.05f) {
            uint b = __float_as_uint(__fmul_rn(s, sig_exact(ctrn[p]))) >> 24;
            if (b) atomicAdd(&h8[b], 1u);
        }
    }
    __syncthreads();
    if (t == 0) {
        uint cum = 0, b1 = 1;
        for (int b = 255; b >= 1; b--) {
            cum += h8[b];
            if (cum >= TOPK) { b1 = (uint)b; break; }
        }
        s_b1 = b1;
    }
    __syncthreads();
    uint b1 = s_b1;
    for (int j = t; j < CPE; j += 1024) {
        int p = j % PP;
        float s = sig_exact(clsn[j]);
        if (s > 0.05f) {
            float score = __fmul_rn(s, sig_exact(ctrn[p]));
            uint sb = __float_as_uint(score);
            if ((sb >> 24) >= b1) {
                int c = j / PP;
                uint i = (uint)(p * NCLS + c);
                ull key = ((ull)sb << 32) | (ull)(0xFFFFFFFFu - i);
                uint pos = atomicAdd(&g_candcnt[n], 1u);
                if (pos < CAP) g_cand[n][pos] = key;
            }
        }
    }
    __syncthreads();
    uint attempted = g_candcnt[n];
    uint M = attempted > CAP ? CAP : attempted;
    refine_core(n, M, loc, reg, info, slist, shist, smisc);
    if (t == 0) { g_flag[n] = 0u; g_candcnt[n] = 0u; }
}

// ---------------- K5: suppression bitmask, 64 blocks -------------------------
__global__ __launch_bounds__(256) void k_mask() {
    __shared__ float4 sob[KPAD];
    __shared__ float  sar[KPAD];
    __shared__ float  slb[KPAD];
    int n = blockIdx.y;
    int t = threadIdx.x;
    for (int q = t; q < KPAD; q += 256) {
        sob[q] = *(const float4*)&g_obox[n][q][0];
        sar[q] = g_area[n][q];
        slb[q] = g_lab[n][q];
    }
    __syncthreads();
    int warp = t >> 5, lane = t & 31;
    for (int rr = 0; rr < 16; rr++) {
        int i = blockIdx.x * 128 + warp * 16 + rr;
        float4 bi = sob[i];
        float ai = sar[i];
        float li = slb[i];
        int w0 = i >> 5;
        uint myword = 0u;
        for (int w = w0; w < 32; w++) {
            int j = w * 32 + lane;
            bool lm = (j > i) && (slb[j] == li);     // cross-class IoU exactly 0
            bool sup = false;
            if (__ballot_sync(0xffffffffu, lm)) {
                if (lm) {
                    float4 bj = sob[j];
                    float wv = fmaxf(__fsub_rn(fminf(bi.z, bj.z), fmaxf(bi.x, bj.x)), 0.0f);
                    float hv = fmaxf(__fsub_rn(fminf(bi.w, bj.w), fmaxf(bi.y, bj.y)), 0.0f);
                    float inter = __fmul_rn(wv, hv);
                    float denom = __fadd_rn(__fsub_rn(__fadd_rn(ai, sar[j]), inter), 1e-9f);
                    sup = inter > __fmul_rn(0.6f, denom);   // iou > 0.6
                }
            }
            uint bits = __ballot_sync(0xffffffffu, sup);
            if (lane == w) myword = bits;
        }
        g_mask[n][i][lane] = (lane >= w0) ? myword : 0u;
    }
}

// ---------------- K6: serial greedy NMS on smem mask + output ----------------
__global__ __launch_bounds__(1024, 1) void k_nms(float* __restrict__ out) {
    extern __shared__ uint smask[];                  // 1024 x 32 = 128 KB
    int n = blockIdx.x;
    int t = threadIdx.x;
    if (t < 600) out[(size_t)n * 600 + t] = 0.0f;
    const uint4* src = (const uint4*)&g_mask[n][0][0];
    uint4* dst = (uint4*)smask;
    for (int q = t; q < KPAD * 8; q += 1024) dst[q] = src[q];
    __syncthreads();
    if (t < 32) {
        int lane = t;
        uint validw = g_validbits[n][lane];
        uint removew = 0u;
        for (int g = 0; g < 32; g++) {
            uint cur_sup = __shfl_sync(0xffffffffu, removew, g);
            uint cur_val = __shfl_sync(0xffffffffu, validw, g);
            uint rowv[32], diag[32];
#pragma unroll
            for (int b = 0; b < 32; b++) {
                rowv[b] = smask[(g * 32 + b) * 32 + lane];
                diag[b] = smask[(g * 32 + b) * 32 + g];
            }
#pragma unroll
            for (int b = 0; b < 32; b++) {
                bool alive = ((cur_val >> b) & 1u) && !((cur_sup >> b) & 1u);
                if (alive) { removew |= rowv[b]; cur_sup |= diag[b]; }
            }
        }
        uint keepw = validw & ~removew;
        int cnt = __popc(keepw);
        int inc = cnt;
        for (int o = 1; o < 32; o <<= 1) {
            int v = __shfl_up_sync(0xffffffffu, inc, o);
            if (lane >= o) inc += v;
        }
        int basei = inc - cnt;
        uint m = keepw;
        while (m) {
            int b = __ffs(m) - 1;
            m &= m - 1;
            int rank = basei + __popc(keepw & ((1u << b) - 1u));
            if (rank < 100) {
                int i = lane * 32 + b;
                float* o6 = out + ((size_t)n * 100 + rank) * 6;
                o6[0] = g_box[n][i][0]; o6[1] = g_box[n][i][1];
                o6[2] = g_box[n][i][2]; o6[3] = g_box[n][i][3];
                o6[4] = g_lab[n][i];    o6[5] = g_sc[n][i];
            }
        }
    }
}

// ---------------- launch -----------------------------------------------------
extern "C" void kernel_launch(void* const* d_in, const int* in_sizes, int n_in,
                              void* d_out, int out_size) {
    const float* loc  = (const float*)d_in[0];
    const float* cls  = (const float*)d_in[1];
    const float* reg  = (const float*)d_in[2];
    const float* ctr  = (const float*)d_in[3];
    const float* info = (const float*)d_in[4];
    float* out = (float*)d_out;
    (void)in_sizes; (void)n_in; (void)out_size;

    cudaFuncSetAttribute(k_nms, cudaFuncAttributeMaxDynamicSharedMemorySize,
                         KPAD * 32 * 4);

    k_sample<<<dim3(SBLK, NIMG), 256>>>(cls, ctr);
    k_compact<<<dim3(15, 10, NIMG), 256>>>(cls, ctr);
    k_refine<<<NIMG, 1024>>>(loc, reg, info);
    k_fallback<<<NIMG, 1024>>>(cls, ctr, loc, reg, info);
    k_mask<<<dim3(8, NIMG), 256>>>();
    k_nms<<<NIMG, 1024, KPAD * 32 * 4>>>(out);
}

// round 8
// speedup vs baseline: 1.7222x; 1.6394x over previous
#include <cuda_runtime.h>
#include <math.h>
#include <stdint.h>

// FCOS post-process, GB300 (sm_103a), round 8 (= round 7 + warp-uniform fix).
// K1 sample (+t14 +xmin by last block/image)
// K2 compact: max-gated 39MB scan, exact rescoring of rare passers
// K3 finish: verify -> select top-256 -> sort -> decode -> 256-mask -> early-stop
//            NMS (needs 100 kept) -> output
// K4 full fallback (guarded; exact rebuild + 1024-wide NMS; never runs here)

#define NIMG 8
#define NCLS 80
#define PP   15200
#define CPE  (NCLS*PP)        // 1216000
#define TOPK 1000
#define KPAD 1024
#define SEL  256              // early-stop NMS window
#define SRT  512              // sort width (SEL + tie slack)
#define CAP  262144
#define CAP2 2048
#define NSAMP 960
#define NITEM (NSAMP*10)
#define SBLK 38
#define TARGET_S 100
#define C0 (-2.9444389791664403f)   // logit(0.05)
typedef unsigned long long ull;
typedef unsigned int uint;

// ---------------- device scratch (module-load zeroed; self-cleaning) ---------
__device__ ull  g_cand[NIMG][CAP];                   // 16 MB
__device__ uint g_hist14[NIMG][4096];
__device__ uint g_candcnt[NIMG];
__device__ uint g_scount[NIMG];
__device__ uint g_T[NIMG];
__device__ uint g_flag[NIMG];                        // candidates incomplete
__device__ uint g_flag2[NIMG];                       // top-256 window insufficient
__device__ float g_xmin[NIMG][PP];
__device__ float g_box [NIMG][KPAD][4];
__device__ float g_obox[NIMG][KPAD][4];
__device__ float g_area[NIMG][KPAD];
__device__ float g_lab [NIMG][KPAD];
__device__ float g_sc  [NIMG][KPAD];
__device__ uint g_validbits[NIMG][32];

__device__ __forceinline__ float sig_exact(float v) {
    return 1.0f / (1.0f + expf(-v));
}
__device__ __forceinline__ float score_apx(float x, float eyp) {
    return __frcp_rn(__fmul_rn(__fadd_rn(1.0f, __expf(-x)), eyp));
}
__device__ __forceinline__ float4 f4max(float4 a, float4 b) {
    return make_float4(fmaxf(a.x, b.x), fmaxf(a.y, b.y),
                      fmaxf(a.z, b.z), fmaxf(a.w, b.w));
}

// ---------------- K1: sampled hist; last block: t14 + xmin table -------------
__global__ __launch_bounds__(256) void k_sample(const float* __restrict__ cls,
                                                const float* __restrict__ ctr) {
    __shared__ uint s_old;
    __shared__ uint ss[256];
    __shared__ float s_edge;
    int n = blockIdx.y;
    int t = threadIdx.x;
    int item = blockIdx.x * 256 + t;
    if (item < NITEM) {
        int k  = item % NSAMP;
        int cb = item / NSAMP;
        int p = (k >> 4) * 253 + (k & 15);           // 60 runs of 16 points
        float eyp = __fadd_rn(1.0f, __expf(-ctr[(size_t)n * PP + p]));
        const float* base = cls + (size_t)n * CPE + p + (size_t)cb * 8 * PP;
        float xs[8];
#pragma unroll
        for (int i = 0; i < 8; i++) xs[i] = base[(size_t)i * PP];
#pragma unroll
        for (int i = 0; i < 8; i++) {
            if (xs[i] > C0) {
                uint b14 = __float_as_uint(score_apx(xs[i], eyp)) >> 18;
                if (b14 > 4095u) b14 = 4095u;
                if (b14) atomicAdd(&g_hist14[n][b14], 1u);
            }
        }
    }
    __threadfence();
    __syncthreads();
    if (t == 0) s_old = atomicAdd(&g_scount[n], 1u);
    __syncthreads();
    if (s_old != SBLK - 1) return;
    uint loc[16]; uint s = 0;
#pragma unroll
    for (int i = 0; i < 16; i++) {
        loc[i] = __ldcg(&g_hist14[n][t * 16 + i]);
        g_hist14[n][t * 16 + i] = 0u;
        s += loc[i];
    }
    ss[t] = s;
    __syncthreads();
    for (int off = 1; off < 256; off <<= 1) {
        uint v = (t + off < 256) ? ss[t + off] : 0u;
        __syncthreads();
        ss[t] += v;
        __syncthreads();
    }
    uint mine = ss[t];
    uint above = (t + 1 < 256) ? ss[t + 1] : 0u;
    if (mine >= TARGET_S && above < TARGET_S) {
        uint cum = above, T = 1;
        for (int i = 15; i >= 0; i--) {
            cum += loc[i];
            if (cum >= TARGET_S) { T = (uint)(t * 16 + i); break; }
        }
        if (T < 1) T = 1;
        uint gate = (T > 2) ? T - 1 : 1u;
        g_T[n] = T;
        s_edge = __uint_as_float(gate << 18);
    }
    if (t == 0) {
        g_scount[n] = 0u;
        if (ss[0] < TARGET_S) {
            g_T[n] = 1;
            s_edge = __uint_as_float(1u << 18);
        }
    }
    __syncthreads();
    float edge = s_edge;
    for (int p = t; p < PP; p += 256) {
        float eyp = __fadd_rn(1.0f, __expf(-ctr[(size_t)n * PP + p]));
        float K = __fdividef(1.0f, __fmul_rn(edge, eyp)) - 1.0f;
        float xm = (K > 0.0f) ? (-__logf(K) - 0.002f) : 3.0e38f;
        g_xmin[n][p] = fmaxf(xm, C0);
    }
}

// ---------------- K2: max-gated full scan ------------------------------------
// grid (15, 10, NIMG): thread owns 4 points (float4) x 8 classes.
__global__ __launch_bounds__(256) void k_compact(const float* __restrict__ cls,
                                                 const float* __restrict__ ctr) {
    int n = blockIdx.z;
    int q = blockIdx.x * 256 + threadIdx.x;
    if (q >= PP / 4) return;
    int pb = q * 4;
    float4 xm4 = *(const float4*)&g_xmin[n][pb];
    float xm[4] = {xm4.x, xm4.y, xm4.z, xm4.w};
    int c0 = blockIdx.y * 8;
    const float* base = cls + (size_t)n * CPE + pb;
    float4 xv[8];
#pragma unroll
    for (int i = 0; i < 8; i++)
        xv[i] = *(const float4*)(base + (size_t)(c0 + i) * PP);
    float4 m4 = xv[0];
#pragma unroll
    for (int i = 1; i < 8; i++) m4 = f4max(m4, xv[i]);
    float mj[4] = {m4.x, m4.y, m4.z, m4.w};
#pragma unroll
    for (int j = 0; j < 4; j++) {
        if (mj[j] >= xm[j]) {                        // rare: some class passes
#pragma unroll
            for (int i = 0; i < 8; i++) {
                float x = (j == 0) ? xv[i].x : (j == 1) ? xv[i].y
                        : (j == 2) ? xv[i].z : xv[i].w;
                if (x >= xm[j]) {
                    float s = sig_exact(x);
                    if (s > 0.05f) {                 // exact candidacy
                        float y = ctr[(size_t)n * PP + pb + j];
                        float score = __fmul_rn(s, sig_exact(y));
                        uint sb = __float_as_uint(score);
                        uint idx = (uint)((pb + j) * NCLS + (c0 + i));
                        ull key = ((ull)sb << 32) | (ull)(0xFFFFFFFFu - idx);
                        uint pos = atomicAdd(&g_candcnt[n], 1u);
                        if (pos < CAP) g_cand[n][pos] = key;
                    }
                }
            }
        }
    }
}

// ---------------- decode helper ----------------------------------------------
__device__ __forceinline__ void decode_one(int n, ull key,
        const float* loc, const float* reg, const float* info,
        float4* box4, float4* ob4, float* area, float* lab, float* sc, bool* valid) {
    float x1 = 0, y1 = 0, x2 = 0, y2 = 0, labf = 0, score = 0;
    float ox1 = 0, oy1 = 0, ox2 = 0, oy2 = 0, ar = 0;
    bool vld = false;
    uint sb = (uint)(key >> 32);
    if (sb) {
        score = __uint_as_float(sb);
        uint i = 0xFFFFFFFFu - (uint)(key & 0xFFFFFFFFull);
        int p = (int)(i / NCLS);
        int c = (int)(i - (uint)(p * NCLS));
        labf = (float)(c + 1);
        float lx = loc[2 * p], ly = loc[2 * p + 1];
        float rl = reg[((size_t)(n * 4 + 0)) * PP + p];
        float rt = reg[((size_t)(n * 4 + 1)) * PP + p];
        float rr = reg[((size_t)(n * 4 + 2)) * PP + p];
        float rb = reg[((size_t)(n * 4 + 3)) * PP + p];
        float hm1 = __fsub_rn(info[2 * n + 0], 1.0f);
        float wm1 = __fsub_rn(info[2 * n + 1], 1.0f);
        x1 = fminf(fmaxf(__fsub_rn(lx, rl), 0.0f), wm1);
        y1 = fminf(fmaxf(__fsub_rn(ly, rt), 0.0f), hm1);
        x2 = fminf(fmaxf(__fadd_rn(lx, rr), 0.0f), wm1);
        y2 = fminf(fmaxf(__fadd_rn(ly, rb), 0.0f), hm1);
        vld = (score > 0.0f) &&
              (__fsub_rn(x2, x1) >= 0.0f) && (__fsub_rn(y2, y1) >= 0.0f);
        float off = __fmul_rn(labf, 1.0e5f);
        ox1 = __fadd_rn(x1, off); oy1 = __fadd_rn(y1, off);
        ox2 = __fadd_rn(x2, off); oy2 = __fadd_rn(y2, off);
        ar = __fmul_rn(fmaxf(__fsub_rn(ox2, ox1), 0.0f),
                       fmaxf(__fsub_rn(oy2, oy1), 0.0f));
    }
    *box4 = make_float4(x1, y1, x2, y2);
    *ob4  = make_float4(ox1, oy1, ox2, oy2);
    *area = ar; *lab = labf; *sc = score; *valid = vld;
}

__device__ __forceinline__ bool iou_sup(float4 bi, float ai, float4 bj, float aj) {
    float wv = fmaxf(__fsub_rn(fminf(bi.z, bj.z), fmaxf(bi.x, bj.x)), 0.0f);
    float hv = fmaxf(__fsub_rn(fminf(bi.w, bj.w), fmaxf(bi.y, bj.y)), 0.0f);
    float inter = __fmul_rn(wv, hv);
    float denom = __fadd_rn(__fsub_rn(__fadd_rn(ai, aj), inter), 1e-9f);
    return inter > __fmul_rn(0.6f, denom);           // iou > 0.6
}

// ---------------- K3: finish (select 256, sort, mask, early-stop NMS) --------
__global__ __launch_bounds__(1024) void k_finish(const float* __restrict__ loc,
                                                 const float* __restrict__ reg,
                                                 const float* __restrict__ info,
                                                 float* __restrict__ out) {
    __shared__ ull slist[SRT];
    __shared__ uint shist[256];
    __shared__ uint smisc[8];
    __shared__ float4 sbox[SEL], sob[SEL];
    __shared__ float sar[SEL], slb[SEL], ssc[SEL];
    __shared__ uint svalid[8];
    __shared__ uint smask[SEL * 8];                  // 8 KB
    __shared__ int s_ok;
    int n = blockIdx.x;
    int t = threadIdx.x;
    if (t < 600) out[(size_t)n * 600 + t] = 0.0f;    // harmless if K4 rewrites
    uint attempted = g_candcnt[n];
    uint M = attempted > CAP ? CAP : attempted;
    if (t == 0) { smisc[3] = 0u; s_ok = 1; }
    __syncthreads();
    // verify completeness to depth >= TOPK (covers K4's full-width needs too)
    uint Vb = g_T[n] << 18;
    uint local = 0;
    for (uint idx = t; idx < M; idx += 1024)
        if ((uint)(g_cand[n][idx] >> 32) >= Vb) local++;
    if (local) atomicAdd(&smisc[3], local);
    __syncthreads();
    if (smisc[3] < TOPK || attempted > CAP) {
        if (t == 0) g_flag[n] = 1u;                  // K4 rebuilds exactly
        return;
    }
    // radix select: exact scorebits threshold for rank SEL (M >= TOPK > SEL)
    if (t == 0) { smisc[0] = 0u; smisc[1] = SEL; smisc[2] = 0u; }
    __syncthreads();
    for (int lvl = 3; lvl >= 0; lvl--) {
        if (t < 256) shist[t] = 0u;
        __syncthreads();
        uint pfx = smisc[0];
        for (uint idx = t; idx < M; idx += 1024) {
            uint bits = (uint)(g_cand[n][idx] >> 32);
            bool cond = (lvl == 3) || ((bits >> ((lvl + 1) * 8)) == pfx);
            if (cond) atomicAdd(&shist[(bits >> (lvl * 8)) & 255u], 1u);
        }
        __syncthreads();
        if (t == 0) {
            uint cum = 0, rr = smisc[1]; int chosen = 0;
            for (int b = 255; b >= 0; b--) {
                cum += shist[b];
                if (cum >= rr) { chosen = b; smisc[1] = rr - (cum - shist[b]); break; }
            }
            smisc[0] = (smisc[0] << 8) | (uint)chosen;
        }
        __syncthreads();
    }
    uint sstar = smisc[0];
    if (t < SRT) slist[t] = 0ull;
    __syncthreads();
    for (uint idx = t; idx < M; idx += 1024) {
        ull key = g_cand[n][idx];
        if ((uint)(key >> 32) >= sstar) {
            uint pos = atomicAdd(&smisc[2], 1u);
            if (pos < SRT) slist[pos] = key;
        }
    }
    __syncthreads();
    if (smisc[2] > SRT) {                            // absurd tie explosion
        if (t == 0) g_flag2[n] = 1u;
        return;
    }
    // bitonic sort SRT descending (threads t < SRT/2 compare)
    for (int k2 = 2; k2 <= SRT; k2 <<= 1) {
        for (int s2 = k2 >> 1; s2 >= 1; s2 >>= 1) {
            if (t < SRT / 2) {
                int i = ((t & ~(s2 - 1)) << 1) | (t & (s2 - 1));
                int l = i | s2;
                ull a = slist[i], b = slist[l];
                bool dir = ((i & k2) == 0);
                if ((a < b) == dir) { slist[i] = b; slist[l] = a; }
            }
            __syncthreads();
        }
    }
    // decode top-SEL
    if (t < SEL) {
        bool vld;
        decode_one(n, slist[t], loc, reg, info,
                   &sbox[t], &sob[t], &sar[t], &slb[t], &ssc[t], &vld);
        uint bal = __ballot_sync(0xffffffffu, vld);
        if ((t & 31) == 0) svalid[t >> 5] = bal;
    }
    __syncthreads();
    // mask 256x256: warp w handles rows 8w..8w+7; lane spans j within word wd
    {
        int warp = t >> 5, lane = t & 31;
#pragma unroll
        for (int r = 0; r < 8; r++) {
            int i = warp * 8 + r;
            float4 bi = sob[i];
            float ai = sar[i];
            float li = slb[i];
#pragma unroll
            for (int wd = 0; wd < 8; wd++) {
                int j = wd * 32 + lane;
                bool sup = false;
                if (j > i && slb[j] == li)
                    sup = iou_sup(bi, ai, sob[j], sar[j]);
                uint bits = __ballot_sync(0xffffffffu, sup);
                if (lane == 0) smask[i * 8 + wd] = bits;
            }
        }
    }
    __syncthreads();
    // early-stop greedy NMS on warp 0 (8 groups of 32)
    if (t < 32) {
        int lane = t;
        uint validw = (lane < 8) ? svalid[lane] : 0u;
        uint removew = 0u;
        for (int g = 0; g < 8; g++) {
            uint cur_sup = __shfl_sync(0xffffffffu, removew, g);
            uint cur_val = __shfl_sync(0xffffffffu, validw, g);
            uint rowv[32], diag[32];
#pragma unroll
            for (int b = 0; b < 32; b++) {
                rowv[b] = (lane < 8) ? smask[(g * 32 + b) * 8 + lane] : 0u;
                diag[b] = smask[(g * 32 + b) * 8 + g];
            }
#pragma unroll
            for (int b = 0; b < 32; b++) {
                bool alive = ((cur_val >> b) & 1u) && !((cur_sup >> b) & 1u);
                if (alive) { removew |= rowv[b]; cur_sup |= diag[b]; }
            }
        }
        uint keepw = validw & ~removew;
        int kv = __popc(keepw);
        int tot = kv;
#pragma unroll
        for (int o = 1; o < 32; o <<= 1)             // FULL-warp reduce: uniform
            tot += __shfl_xor_sync(0xffffffffu, tot, o);
        if (tot >= 100) {                            // warp-uniform branch now
            int inc = kv;
            for (int o = 1; o < 32; o <<= 1) {
                int v = __shfl_up_sync(0xffffffffu, inc, o);
                if (lane >= o) inc += v;
            }
            int basei = inc - kv;
            uint m = keepw;
            while (m) {
                int b = __ffs(m) - 1;
                m &= m - 1;
                int rank = basei + __popc(keepw & ((1u << b) - 1u));
                if (rank < 100) {
                    int i = lane * 32 + b;
                    float* o6 = out + ((size_t)n * 100 + rank) * 6;
                    float4 bx = sbox[i];
                    o6[0] = bx.x; o6[1] = bx.y; o6[2] = bx.z; o6[3] = bx.w;
                    o6[4] = slb[i]; o6[5] = ssc[i];
                }
            }
        } else if (lane == 0) {
            s_ok = 0;                                // need full-width NMS
        }
    }
    __syncthreads();
    if (!s_ok) {
        if (t == 0) g_flag2[n] = 1u;
        return;
    }
    if (t == 0) g_candcnt[n] = 0u;                   // success: restore state
}

// ---------------- shared full refine core (K4 only) --------------------------
__device__ void refine_core(int n, uint M,
                            const float* __restrict__ loc,
                            const float* __restrict__ reg,
                            const float* __restrict__ info,
                            ull* slist, uint* shist, uint* smisc) {
    int t = threadIdx.x;
    if (M <= CAP2) {
        for (int q = t; q < CAP2; q += 1024)
            slist[q] = (q < (int)M) ? g_cand[n][q] : 0ull;
        __syncthreads();
    } else {
        if (t == 0) { smisc[0] = 0u; smisc[1] = TOPK; smisc[2] = 0u; }
        __syncthreads();
        for (int lvl = 3; lvl >= 0; lvl--) {
            if (t < 256) shist[t] = 0u;
            __syncthreads();
            uint pfx = smisc[0];
            for (uint idx = t; idx < M; idx += 1024) {
                uint bits = (uint)(g_cand[n][idx] >> 32);
                bool cond = (lvl == 3) || ((bits >> ((lvl + 1) * 8)) == pfx);
                if (cond) atomicAdd(&shist[(bits >> (lvl * 8)) & 255u], 1u);
            }
            __syncthreads();
            if (t == 0) {
                uint cum = 0, rr = smisc[1]; int chosen = 0;
                for (int b = 255; b >= 0; b--) {
                    cum += shist[b];
                    if (cum >= rr) { chosen = b; smisc[1] = rr - (cum - shist[b]); break; }
                }
                smisc[0] = (smisc[0] << 8) | (uint)chosen;
            }
            __syncthreads();
        }
        uint sstar = smisc[0];
        for (int q = t; q < CAP2; q += 1024) slist[q] = 0ull;
        __syncthreads();
        for (uint idx = t; idx < M; idx += 1024) {
            ull key = g_cand[n][idx];
            if ((uint)(key >> 32) >= sstar) {
                uint pos = atomicAdd(&smisc[2], 1u);
                if (pos < CAP2) slist[pos] = key;
            }
        }
        __syncthreads();
    }
    for (int k2 = 2; k2 <= CAP2; k2 <<= 1) {
        for (int s2 = k2 >> 1; s2 >= 1; s2 >>= 1) {
            int i = ((t & ~(s2 - 1)) << 1) | (t & (s2 - 1));
            int l = i | s2;
            ull a = slist[i], b = slist[l];
            bool dir = ((i & k2) == 0);
            if ((a < b) == dir) { slist[i] = b; slist[l] = a; }
            __syncthreads();
        }
    }
    bool vld = false;
    float4 bx, ob; float ar, lb, sc;
    if (t < TOPK) {
        decode_one(n, slist[t], loc, reg, info, &bx, &ob, &ar, &lb, &sc, &vld);
    } else {
        bx = make_float4(0, 0, 0, 0); ob = bx; ar = 0; lb = 0; sc = 0;
    }
    *(float4*)&g_box[n][t][0] = bx;
    *(float4*)&g_obox[n][t][0] = ob;
    g_area[n][t] = ar; g_lab[n][t] = lb; g_sc[n][t] = sc;
    uint bal = __ballot_sync(0xffffffffu, vld);
    if ((t & 31) == 0) g_validbits[n][t >> 5] = bal;
}

// ---------------- K4: full fallback (guarded; never in practice) -------------
__global__ __launch_bounds__(1024, 1) void k_fallback(const float* __restrict__ cls,
                                                      const float* __restrict__ ctr,
                                                      const float* __restrict__ loc,
                                                      const float* __restrict__ reg,
                                                      const float* __restrict__ info,
                                                      float* __restrict__ out) {
    int n = blockIdx.x;
    if (!g_flag[n] && !g_flag2[n]) return;
    extern __shared__ uint smaskd[];                 // 1024x32 words = 128 KB
    __shared__ ull slist[CAP2];
    __shared__ uint shist[256];
    __shared__ uint smisc[4];
    __shared__ uint h8[256];
    __shared__ uint s_b1;
    __shared__ float4 sob[KPAD];
    __shared__ float sar[KPAD], slb[KPAD];
    int t = threadIdx.x;
    if (g_flag[n]) {                                 // exact candidate rebuild
        if (t < 256) h8[t] = 0u;
        if (t == 0) g_candcnt[n] = 0u;
        __syncthreads();
        const float* clsn = cls + (size_t)n * CPE;
        const float* ctrn = ctr + (size_t)n * PP;
        for (int j = t; j < CPE; j += 1024) {
            int p = j % PP;
            float s = sig_exact(clsn[j]);
            if (s > 0.05f) {
                uint b = __float_as_uint(__fmul_rn(s, sig_exact(ctrn[p]))) >> 24;
                if (b) atomicAdd(&h8[b], 1u);
            }
        }
        __syncthreads();
        if (t == 0) {
            uint cum = 0, b1 = 1;
            for (int b = 255; b >= 1; b--) {
                cum += h8[b];
                if (cum >= TOPK) { b1 = (uint)b; break; }
            }
            s_b1 = b1;
        }
        __syncthreads();
        uint b1 = s_b1;
        for (int j = t; j < CPE; j += 1024) {
            int p = j % PP;
            float s = sig_exact(clsn[j]);
            if (s > 0.05f) {
                float score = __fmul_rn(s, sig_exact(ctrn[p]));
                uint sb = __float_as_uint(score);
                if ((sb >> 24) >= b1) {
                    int c = j / PP;
                    uint i = (uint)(p * NCLS + c);
                    ull key = ((ull)sb << 32) | (ull)(0xFFFFFFFFu - i);
                    uint pos = atomicAdd(&g_candcnt[n], 1u);
                    if (pos < CAP) g_cand[n][pos] = key;
                }
            }
        }
        __syncthreads();
    }
    uint attempted = g_candcnt[n];
    uint M = attempted > CAP ? CAP : attempted;
    refine_core(n, M, loc, reg, info, slist, shist, smisc);
    __syncthreads();
    // full 1024-wide mask into dynamic smem
    if (t < 600) out[(size_t)n * 600 + t] = 0.0f;
    sob[t] = *(float4*)&g_obox[n][t][0];
    sar[t] = g_area[n][t];
    slb[t] = g_lab[n][t];
    __syncthreads();
    int warp = t >> 5, lane = t & 31;
    for (int r = 0; r < 32; r++) {
        int i = r * 32 + warp;
        float4 bi = sob[i];
        float ai = sar[i];
        float li = slb[i];
        uint myword = 0u;
        for (int w = r; w < 32; w++) {
            int j = w * 32 + lane;
            bool sup = false;
            if (j > i && slb[j] == li)
                sup = iou_sup(bi, ai, sob[j], sar[j]);
            uint bits = __ballot_sync(0xffffffffu, sup);
            if (lane == w) myword = bits;
        }
        smaskd[i * 32 + lane] = (lane >= r) ? myword : 0u;
    }
    __syncthreads();
    if (t < 32) {
        uint validw = g_validbits[n][lane];
        uint removew = 0u;
        for (int g = 0; g < 32; g++) {
            uint cur_sup = __shfl_sync(0xffffffffu, removew, g);
            uint cur_val = __shfl_sync(0xffffffffu, validw, g);
            uint rowv[32], diag[32];
#pragma unroll
            for (int b = 0; b < 32; b++) {
                rowv[b] = smaskd[(g * 32 + b) * 32 + lane];
                diag[b] = smaskd[(g * 32 + b) * 32 + g];
            }
#pragma unroll
            for (int b = 0; b < 32; b++) {
                bool alive = ((cur_val >> b) & 1u) && !((cur_sup >> b) & 1u);
                if (alive) { removew |= rowv[b]; cur_sup |= diag[b]; }
            }
        }
        uint keepw = validw & ~removew;
        int cnt = __popc(keepw);
        int inc = cnt;
        for (int o = 1; o < 32; o <<= 1) {
            int v = __shfl_up_sync(0xffffffffu, inc, o);
            if (lane >= o) inc += v;
        }
        int basei = inc - cnt;
        uint m = keepw;
        while (m) {
            int b = __ffs(m) - 1;
            m &= m - 1;
            int rank = basei + __popc(keepw & ((1u << b) - 1u));
            if (rank < 100) {
                int i = lane * 32 + b;
                float* o6 = out + ((size_t)n * 100 + rank) * 6;
                o6[0] = g_box[n][i][0]; o6[1] = g_box[n][i][1];
                o6[2] = g_box[n][i][2]; o6[3] = g_box[n][i][3];
                o6[4] = g_lab[n][i];    o6[5] = g_sc[n][i];
            }
        }
    }
    __syncthreads();
    if (t == 0) { g_flag[n] = 0u; g_flag2[n] = 0u; g_candcnt[n] = 0u; }
}

// ---------------- launch -----------------------------------------------------
extern "C" void kernel_launch(void* const* d_in, const int* in_sizes, int n_in,
                              void* d_out, int out_size) {
    const float* loc  = (const float*)d_in[0];
    const float* cls  = (const float*)d_in[1];
    const float* reg  = (const float*)d_in[2];
    const float* ctr  = (const float*)d_in[3];
    const float* info = (const float*)d_in[4];
    float* out = (float*)d_out;
    (void)in_sizes; (void)n_in; (void)out_size;

    cudaFuncSetAttribute(k_fallback, cudaFuncAttributeMaxDynamicSharedMemorySize,
                         KPAD * 32 * 4);

    k_sample<<<dim3(SBLK, NIMG), 256>>>(cls, ctr);
    k_compact<<<dim3(15, 10, NIMG), 256>>>(cls, ctr);
    k_finish<<<NIMG, 1024>>>(loc, reg, info, out);
    k_fallback<<<NIMG, 1024, KPAD * 32 * 4>>>(cls, ctr, loc, reg, info, out);
}

// round 9
// speedup vs baseline: 1.8859x; 1.0951x over previous
#include <cuda_runtime.h>
#include <math.h>
#include <stdint.h>

// FCOS post-process, GB300 (sm_103a), round 9: 3 kernels.
// K1 sample (+t14 +xmin by last block/image)
// K2 compact: max-gated 39MB scan, 4 classes/thread (MLP_p1=4, 2 waves)
// K3 finish: verify -> top-256 early-stop NMS -> output;
//            inline guarded fallback (exact rebuild + 1024-wide NMS)

#define NIMG 8
#define NCLS 80
#define PP   15200
#define CPE  (NCLS*PP)        // 1216000
#define TOPK 1000
#define KPAD 1024
#define SEL  256              // early-stop NMS window
#define SRT  512              // sort width (SEL + tie slack)
#define CAP  262144
#define CAP2 2048
#define NSAMP 960
#define NITEM (NSAMP*10)
#define SBLK 38
#define TARGET_S 100
#define C0 (-2.9444389791664403f)   // logit(0.05)
typedef unsigned long long ull;
typedef unsigned int uint;

// ---------------- device scratch (module-load zeroed; self-cleaning) ---------
__device__ ull  g_cand[NIMG][CAP];                   // 16 MB
__device__ uint g_hist14[NIMG][4096];
__device__ uint g_candcnt[NIMG];
__device__ uint g_scount[NIMG];
__device__ uint g_T[NIMG];
__device__ float g_xmin[NIMG][PP];
__device__ float g_box [NIMG][KPAD][4];
__device__ float g_obox[NIMG][KPAD][4];
__device__ float g_area[NIMG][KPAD];
__device__ float g_lab [NIMG][KPAD];
__device__ float g_sc  [NIMG][KPAD];
__device__ uint g_validbits[NIMG][32];

__device__ __forceinline__ float sig_exact(float v) {
    return 1.0f / (1.0f + expf(-v));
}
__device__ __forceinline__ float score_apx(float x, float eyp) {
    return __frcp_rn(__fmul_rn(__fadd_rn(1.0f, __expf(-x)), eyp));
}
__device__ __forceinline__ float4 f4max(float4 a, float4 b) {
    return make_float4(fmaxf(a.x, b.x), fmaxf(a.y, b.y),
                      fmaxf(a.z, b.z), fmaxf(a.w, b.w));
}

// ---------------- K1: sampled hist; last block: t14 + xmin table -------------
__global__ __launch_bounds__(256) void k_sample(const float* __restrict__ cls,
                                                const float* __restrict__ ctr) {
    __shared__ uint s_old;
    __shared__ uint ss[256];
    __shared__ float s_edge;
    int n = blockIdx.y;
    int t = threadIdx.x;
    int item = blockIdx.x * 256 + t;
    if (item < NITEM) {
        int k  = item % NSAMP;
        int cb = item / NSAMP;
        int p = (k >> 4) * 253 + (k & 15);           // 60 runs of 16 points
        float eyp = __fadd_rn(1.0f, __expf(-ctr[(size_t)n * PP + p]));
        const float* base = cls + (size_t)n * CPE + p + (size_t)cb * 8 * PP;
        float xs[8];
#pragma unroll
        for (int i = 0; i < 8; i++) xs[i] = base[(size_t)i * PP];
#pragma unroll
        for (int i = 0; i < 8; i++) {
            if (xs[i] > C0) {
                uint b14 = __float_as_uint(score_apx(xs[i], eyp)) >> 18;
                if (b14 > 4095u) b14 = 4095u;
                if (b14) atomicAdd(&g_hist14[n][b14], 1u);
            }
        }
    }
    __threadfence();
    __syncthreads();
    if (t == 0) s_old = atomicAdd(&g_scount[n], 1u);
    __syncthreads();
    if (s_old != SBLK - 1) return;
    uint loc[16]; uint s = 0;
#pragma unroll
    for (int i = 0; i < 16; i++) {
        loc[i] = __ldcg(&g_hist14[n][t * 16 + i]);
        g_hist14[n][t * 16 + i] = 0u;
        s += loc[i];
    }
    ss[t] = s;
    __syncthreads();
    for (int off = 1; off < 256; off <<= 1) {
        uint v = (t + off < 256) ? ss[t + off] : 0u;
        __syncthreads();
        ss[t] += v;
        __syncthreads();
    }
    uint mine = ss[t];
    uint above = (t + 1 < 256) ? ss[t + 1] : 0u;
    if (mine >= TARGET_S && above < TARGET_S) {
        uint cum = above, T = 1;
        for (int i = 15; i >= 0; i--) {
            cum += loc[i];
            if (cum >= TARGET_S) { T = (uint)(t * 16 + i); break; }
        }
        if (T < 1) T = 1;
        uint gate = (T > 2) ? T - 1 : 1u;
        g_T[n] = T;
        s_edge = __uint_as_float(gate << 18);
    }
    if (t == 0) {
        g_scount[n] = 0u;
        if (ss[0] < TARGET_S) {
            g_T[n] = 1;
            s_edge = __uint_as_float(1u << 18);
        }
    }
    __syncthreads();
    float edge = s_edge;
    for (int p = t; p < PP; p += 256) {
        float eyp = __fadd_rn(1.0f, __expf(-ctr[(size_t)n * PP + p]));
        float K = __fdividef(1.0f, __fmul_rn(edge, eyp)) - 1.0f;
        float xm = (K > 0.0f) ? (-__logf(K) - 0.002f) : 3.0e38f;
        g_xmin[n][p] = fmaxf(xm, C0);
    }
}

// ---------------- K2: max-gated full scan, 4 classes/thread ------------------
// grid (15, 20, NIMG): thread owns 4 points (float4) x 4 classes (MLP_p1=4).
__global__ __launch_bounds__(256) void k_compact(const float* __restrict__ cls,
                                                 const float* __restrict__ ctr) {
    int n = blockIdx.z;
    int q = blockIdx.x * 256 + threadIdx.x;
    if (q >= PP / 4) return;
    int pb = q * 4;
    float4 xm4 = *(const float4*)&g_xmin[n][pb];
    float xm[4] = {xm4.x, xm4.y, xm4.z, xm4.w};
    int c0 = blockIdx.y * 4;
    const float* base = cls + (size_t)n * CPE + pb;
    float4 xv[4];
#pragma unroll
    for (int i = 0; i < 4; i++)
        xv[i] = *(const float4*)(base + (size_t)(c0 + i) * PP);
    float4 m4 = f4max(f4max(xv[0], xv[1]), f4max(xv[2], xv[3]));
    float mj[4] = {m4.x, m4.y, m4.z, m4.w};
#pragma unroll
    for (int j = 0; j < 4; j++) {
        if (mj[j] >= xm[j]) {                        // rare: some class passes
#pragma unroll
            for (int i = 0; i < 4; i++) {
                float x = (j == 0) ? xv[i].x : (j == 1) ? xv[i].y
                        : (j == 2) ? xv[i].z : xv[i].w;
                if (x >= xm[j]) {
                    float s = sig_exact(x);
                    if (s > 0.05f) {                 // exact candidacy
                        float y = ctr[(size_t)n * PP + pb + j];
                        float score = __fmul_rn(s, sig_exact(y));
                        uint sb = __float_as_uint(score);
                        uint idx = (uint)((pb + j) * NCLS + (c0 + i));
                        ull key = ((ull)sb << 32) | (ull)(0xFFFFFFFFu - idx);
                        uint pos = atomicAdd(&g_candcnt[n], 1u);
                        if (pos < CAP) g_cand[n][pos] = key;
                    }
                }
            }
        }
    }
}

// ---------------- decode helper ----------------------------------------------
__device__ __forceinline__ void decode_one(int n, ull key,
        const float* loc, const float* reg, const float* info,
        float4* box4, float4* ob4, float* area, float* lab, float* sc, bool* valid) {
    float x1 = 0, y1 = 0, x2 = 0, y2 = 0, labf = 0, score = 0;
    float ox1 = 0, oy1 = 0, ox2 = 0, oy2 = 0, ar = 0;
    bool vld = false;
    uint sb = (uint)(key >> 32);
    if (sb) {
        score = __uint_as_float(sb);
        uint i = 0xFFFFFFFFu - (uint)(key & 0xFFFFFFFFull);
        int p = (int)(i / NCLS);
        int c = (int)(i - (uint)(p * NCLS));
        labf = (float)(c + 1);
        float lx = loc[2 * p], ly = loc[2 * p + 1];
        float rl = reg[((size_t)(n * 4 + 0)) * PP + p];
        float rt = reg[((size_t)(n * 4 + 1)) * PP + p];
        float rr = reg[((size_t)(n * 4 + 2)) * PP + p];
        float rb = reg[((size_t)(n * 4 + 3)) * PP + p];
        float hm1 = __fsub_rn(info[2 * n + 0], 1.0f);
        float wm1 = __fsub_rn(info[2 * n + 1], 1.0f);
        x1 = fminf(fmaxf(__fsub_rn(lx, rl), 0.0f), wm1);
        y1 = fminf(fmaxf(__fsub_rn(ly, rt), 0.0f), hm1);
        x2 = fminf(fmaxf(__fadd_rn(lx, rr), 0.0f), wm1);
        y2 = fminf(fmaxf(__fadd_rn(ly, rb), 0.0f), hm1);
        vld = (score > 0.0f) &&
              (__fsub_rn(x2, x1) >= 0.0f) && (__fsub_rn(y2, y1) >= 0.0f);
        float off = __fmul_rn(labf, 1.0e5f);
        ox1 = __fadd_rn(x1, off); oy1 = __fadd_rn(y1, off);
        ox2 = __fadd_rn(x2, off); oy2 = __fadd_rn(y2, off);
        ar = __fmul_rn(fmaxf(__fsub_rn(ox2, ox1), 0.0f),
                       fmaxf(__fsub_rn(oy2, oy1), 0.0f));
    }
    *box4 = make_float4(x1, y1, x2, y2);
    *ob4  = make_float4(ox1, oy1, ox2, oy2);
    *area = ar; *lab = labf; *sc = score; *valid = vld;
}

__device__ __forceinline__ bool iou_sup(float4 bi, float ai, float4 bj, float aj) {
    float wv = fmaxf(__fsub_rn(fminf(bi.z, bj.z), fmaxf(bi.x, bj.x)), 0.0f);
    float hv = fmaxf(__fsub_rn(fminf(bi.w, bj.w), fmaxf(bi.y, bj.y)), 0.0f);
    float inter = __fmul_rn(wv, hv);
    float denom = __fadd_rn(__fsub_rn(__fadd_rn(ai, aj), inter), 1e-9f);
    return inter > __fmul_rn(0.6f, denom);           // iou > 0.6
}

// ---------------- full refine (slow path only) -------------------------------
__device__ void refine_core(int n, uint M,
                            const float* __restrict__ loc,
                            const float* __restrict__ reg,
                            const float* __restrict__ info,
                            ull* slist, uint* shist, uint* smisc) {
    int t = threadIdx.x;
    if (M <= CAP2) {
        for (int q = t; q < CAP2; q += 1024)
            slist[q] = (q < (int)M) ? g_cand[n][q] : 0ull;
        __syncthreads();
    } else {
        if (t == 0) { smisc[0] = 0u; smisc[1] = TOPK; smisc[2] = 0u; }
        __syncthreads();
        for (int lvl = 3; lvl >= 0; lvl--) {
            if (t < 256) shist[t] = 0u;
            __syncthreads();
            uint pfx = smisc[0];
            for (uint idx = t; idx < M; idx += 1024) {
                uint bits = (uint)(g_cand[n][idx] >> 32);
                bool cond = (lvl == 3) || ((bits >> ((lvl + 1) * 8)) == pfx);
                if (cond) atomicAdd(&shist[(bits >> (lvl * 8)) & 255u], 1u);
            }
            __syncthreads();
            if (t == 0) {
                uint cum = 0, rr = smisc[1]; int chosen = 0;
                for (int b = 255; b >= 0; b--) {
                    cum += shist[b];
                    if (cum >= rr) { chosen = b; smisc[1] = rr - (cum - shist[b]); break; }
                }
                smisc[0] = (smisc[0] << 8) | (uint)chosen;
            }
            __syncthreads();
        }
        uint sstar = smisc[0];
        for (int q = t; q < CAP2; q += 1024) slist[q] = 0ull;
        __syncthreads();
        for (uint idx = t; idx < M; idx += 1024) {
            ull key = g_cand[n][idx];
            if ((uint)(key >> 32) >= sstar) {
                uint pos = atomicAdd(&smisc[2], 1u);
                if (pos < CAP2) slist[pos] = key;
            }
        }
        __syncthreads();
    }
    for (int k2 = 2; k2 <= CAP2; k2 <<= 1) {
        for (int s2 = k2 >> 1; s2 >= 1; s2 >>= 1) {
            int i = ((t & ~(s2 - 1)) << 1) | (t & (s2 - 1));
            int l = i | s2;
            ull a = slist[i], b = slist[l];
            bool dir = ((i & k2) == 0);
            if ((a < b) == dir) { slist[i] = b; slist[l] = a; }
            __syncthreads();
        }
    }
    bool vld = false;
    float4 bx, ob; float ar, lb, sc;
    if (t < TOPK) {
        decode_one(n, slist[t], loc, reg, info, &bx, &ob, &ar, &lb, &sc, &vld);
    } else {
        bx = make_float4(0, 0, 0, 0); ob = bx; ar = 0; lb = 0; sc = 0;
    }
    *(float4*)&g_box[n][t][0] = bx;
    *(float4*)&g_obox[n][t][0] = ob;
    g_area[n][t] = ar; g_lab[n][t] = lb; g_sc[n][t] = sc;
    uint bal = __ballot_sync(0xffffffffu, vld);
    if ((t & 31) == 0) g_validbits[n][t >> 5] = bal;
}

// ---------------- K3: finish (fast top-256 path + inline full fallback) ------
__global__ __launch_bounds__(1024, 1) void k_finish(const float* __restrict__ cls,
                                                    const float* __restrict__ ctr,
                                                    const float* __restrict__ loc,
                                                    const float* __restrict__ reg,
                                                    const float* __restrict__ info,
                                                    float* __restrict__ out) {
    extern __shared__ uint smaskd[];                 // 128 KB (full path mask)
    __shared__ ull slist[CAP2];                      // 16 KB (fast uses [0,SRT))
    __shared__ uint shist[256];
    __shared__ uint smisc[8];
    __shared__ float4 sbox[SEL], sob[SEL];
    __shared__ float sar[SEL], slb[SEL], ssc[SEL];
    __shared__ uint svalid[8];
    __shared__ uint smask[SEL * 8];                  // 8 KB
    __shared__ int s_path;                           // 0 fast-ok, 1 rebuild, 2 full-nms
    __shared__ float4 sobF[KPAD];
    __shared__ float sarF[KPAD], slbF[KPAD];
    int n = blockIdx.x;
    int t = threadIdx.x;
    int lane = t & 31;
    if (t < 600) out[(size_t)n * 600 + t] = 0.0f;
    uint attempted = g_candcnt[n];
    uint M = attempted > CAP ? CAP : attempted;
    if (t == 0) { smisc[3] = 0u; s_path = 0; }
    __syncthreads();
    // verify completeness to depth >= TOPK
    {
        uint Vb = g_T[n] << 18;
        uint local = 0;
        for (uint idx = t; idx < M; idx += 1024)
            if ((uint)(g_cand[n][idx] >> 32) >= Vb) local++;
        if (local) atomicAdd(&smisc[3], local);
    }
    __syncthreads();
    if (smisc[3] < TOPK || attempted > CAP) {
        if (t == 0) s_path = 1;
    }
    __syncthreads();
    if (s_path == 0) {
        // ---- fast path: radix select exact rank-SEL threshold ----
        if (t == 0) { smisc[0] = 0u; smisc[1] = SEL; smisc[2] = 0u; }
        __syncthreads();
        for (int lvl = 3; lvl >= 0; lvl--) {
            if (t < 256) shist[t] = 0u;
            __syncthreads();
            uint pfx = smisc[0];
            for (uint idx = t; idx < M; idx += 1024) {
                uint bits = (uint)(g_cand[n][idx] >> 32);
                bool cond = (lvl == 3) || ((bits >> ((lvl + 1) * 8)) == pfx);
                if (cond) atomicAdd(&shist[(bits >> (lvl * 8)) & 255u], 1u);
            }
            __syncthreads();
            if (t == 0) {
                uint cum = 0, rr = smisc[1]; int chosen = 0;
                for (int b = 255; b >= 0; b--) {
                    cum += shist[b];
                    if (cum >= rr) { chosen = b; smisc[1] = rr - (cum - shist[b]); break; }
                }
                smisc[0] = (smisc[0] << 8) | (uint)chosen;
            }
            __syncthreads();
        }
        uint sstar = smisc[0];
        if (t < SRT) slist[t] = 0ull;
        __syncthreads();
        for (uint idx = t; idx < M; idx += 1024) {
            ull key = g_cand[n][idx];
            if ((uint)(key >> 32) >= sstar) {
                uint pos = atomicAdd(&smisc[2], 1u);
                if (pos < SRT) slist[pos] = key;
            }
        }
        __syncthreads();
        if (smisc[2] > SRT) {                        // absurd tie explosion
            if (t == 0) s_path = 2;
        }
        __syncthreads();
        if (s_path == 0) {
            for (int k2 = 2; k2 <= SRT; k2 <<= 1) {
                for (int s2 = k2 >> 1; s2 >= 1; s2 >>= 1) {
                    if (t < SRT / 2) {
                        int i = ((t & ~(s2 - 1)) << 1) | (t & (s2 - 1));
                        int l = i | s2;
                        ull a = slist[i], b = slist[l];
                        bool dir = ((i & k2) == 0);
                        if ((a < b) == dir) { slist[i] = b; slist[l] = a; }
                    }
                    __syncthreads();
                }
            }
            if (t < SEL) {
                bool vld;
                decode_one(n, slist[t], loc, reg, info,
                           &sbox[t], &sob[t], &sar[t], &slb[t], &ssc[t], &vld);
                uint bal = __ballot_sync(0xffffffffu, vld);
                if ((t & 31) == 0) svalid[t >> 5] = bal;
            }
            __syncthreads();
            {
                int warp = t >> 5;
#pragma unroll
                for (int r = 0; r < 8; r++) {
                    int i = warp * 8 + r;
                    float4 bi = sob[i];
                    float ai = sar[i];
                    float li = slb[i];
#pragma unroll
                    for (int wd = 0; wd < 8; wd++) {
                        int j = wd * 32 + lane;
                        bool sup = false;
                        if (j > i && slb[j] == li)
                            sup = iou_sup(bi, ai, sob[j], sar[j]);
                        uint bits = __ballot_sync(0xffffffffu, sup);
                        if (lane == 0) smask[i * 8 + wd] = bits;
                    }
                }
            }
            __syncthreads();
            if (t < 32) {
                uint validw = (lane < 8) ? svalid[lane] : 0u;
                uint removew = 0u;
                for (int g = 0; g < 8; g++) {
                    uint cur_sup = __shfl_sync(0xffffffffu, removew, g);
                    uint cur_val = __shfl_sync(0xffffffffu, validw, g);
                    uint rowv[32], diag[32];
#pragma unroll
                    for (int b = 0; b < 32; b++) {
                        rowv[b] = (lane < 8) ? smask[(g * 32 + b) * 8 + lane] : 0u;
                        diag[b] = smask[(g * 32 + b) * 8 + g];
                    }
#pragma unroll
                    for (int b = 0; b < 32; b++) {
                        bool alive = ((cur_val >> b) & 1u) && !((cur_sup >> b) & 1u);
                        if (alive) { removew |= rowv[b]; cur_sup |= diag[b]; }
                    }
                }
                uint keepw = validw & ~removew;
                int kv = __popc(keepw);
                int tot = kv;
#pragma unroll
                for (int o = 1; o < 32; o <<= 1)     // full-warp: uniform tot
                    tot += __shfl_xor_sync(0xffffffffu, tot, o);
                if (tot >= 100) {
                    int inc = kv;
                    for (int o = 1; o < 32; o <<= 1) {
                        int v = __shfl_up_sync(0xffffffffu, inc, o);
                        if (lane >= o) inc += v;
                    }
                    int basei = inc - kv;
                    uint m = keepw;
                    while (m) {
                        int b = __ffs(m) - 1;
                        m &= m - 1;
                        int rank = basei + __popc(keepw & ((1u << b) - 1u));
                        if (rank < 100) {
                            int i = lane * 32 + b;
                            float* o6 = out + ((size_t)n * 100 + rank) * 6;
                            float4 bx = sbox[i];
                            o6[0] = bx.x; o6[1] = bx.y; o6[2] = bx.z; o6[3] = bx.w;
                            o6[4] = slb[i]; o6[5] = ssc[i];
                        }
                    }
                } else if (lane == 0) {
                    s_path = 2;                      // need full-width NMS
                }
            }
            __syncthreads();
        }
    }
    if (s_path == 0) {
        if (t == 0) g_candcnt[n] = 0u;
        return;                                      // fast path done
    }
    // ================= slow path (guarded; never in practice) =================
    if (s_path == 1) {                               // exact candidate rebuild
        if (t < 256) shist[t] = 0u;
        if (t == 0) g_candcnt[n] = 0u;
        __syncthreads();
        const float* clsn = cls + (size_t)n * CPE;
        const float* ctrn = ctr + (size_t)n * PP;
        for (int j = t; j < CPE; j += 1024) {
            int p = j % PP;
            float s = sig_exact(clsn[j]);
            if (s > 0.05f) {
                uint b = __float_as_uint(__fmul_rn(s, sig_exact(ctrn[p]))) >> 24;
                if (b) atomicAdd(&shist[b], 1u);
            }
        }
        __syncthreads();
        if (t == 0) {
            uint cum = 0, b1 = 1;
            for (int b = 255; b >= 1; b--) {
                cum += shist[b];
                if (cum >= TOPK) { b1 = (uint)b; break; }
            }
            smisc[4] = b1;
        }
        __syncthreads();
        uint b1 = smisc[4];
        for (int j = t; j < CPE; j += 1024) {
            int p = j % PP;
            float s = sig_exact(clsn[j]);
            if (s > 0.05f) {
                float score = __fmul_rn(s, sig_exact(ctrn[p]));
                uint sb = __float_as_uint(score);
                if ((sb >> 24) >= b1) {
                    int c = j / PP;
                    uint i = (uint)(p * NCLS + c);
                    ull key = ((ull)sb << 32) | (ull)(0xFFFFFFFFu - i);
                    uint pos = atomicAdd(&g_candcnt[n], 1u);
                    if (pos < CAP) g_cand[n][pos] = key;
                }
            }
        }
        __syncthreads();
        attempted = g_candcnt[n];
        M = attempted > CAP ? CAP : attempted;
    }
    refine_core(n, M, loc, reg, info, slist, shist, smisc);
    __syncthreads();
    if (t < 600) out[(size_t)n * 600 + t] = 0.0f;    // re-zero (fast may have run)
    sobF[t] = *(float4*)&g_obox[n][t][0];
    sarF[t] = g_area[n][t];
    slbF[t] = g_lab[n][t];
    __syncthreads();
    int warp = t >> 5;
    for (int r = 0; r < 32; r++) {
        int i = r * 32 + warp;
        float4 bi = sobF[i];
        float ai = sarF[i];
        float li = slbF[i];
        uint myword = 0u;
        for (int w = r; w < 32; w++) {
            int j = w * 32 + lane;
            bool sup = false;
            if (j > i && slbF[j] == li)
                sup = iou_sup(bi, ai, sobF[j], sarF[j]);
            uint bits = __ballot_sync(0xffffffffu, sup);
            if (lane == w) myword = bits;
        }
        smaskd[i * 32 + lane] = (lane >= r) ? myword : 0u;
    }
    __syncthreads();
    if (t < 32) {
        uint validw = g_validbits[n][lane];
        uint removew = 0u;
        for (int g = 0; g < 32; g++) {
            uint cur_sup = __shfl_sync(0xffffffffu, removew, g);
            uint cur_val = __shfl_sync(0xffffffffu, validw, g);
            uint rowv[32], diag[32];
#pragma unroll
            for (int b = 0; b < 32; b++) {
                rowv[b] = smaskd[(g * 32 + b) * 32 + lane];
                diag[b] = smaskd[(g * 32 + b) * 32 + g];
            }
#pragma unroll
            for (int b = 0; b < 32; b++) {
                bool alive = ((cur_val >> b) & 1u) && !((cur_sup >> b) & 1u);
                if (alive) { removew |= rowv[b]; cur_sup |= diag[b]; }
            }
        }
        uint keepw = validw & ~removew;
        int cnt = __popc(keepw);
        int inc = cnt;
        for (int o = 1; o < 32; o <<= 1) {
            int v = __shfl_up_sync(0xffffffffu, inc, o);
            if (lane >= o) inc += v;
        }
        int basei = inc - cnt;
        uint m = keepw;
        while (m) {
            int b = __ffs(m) - 1;
            m &= m - 1;
            int rank = basei + __popc(keepw & ((1u << b) - 1u));
            if (rank < 100) {
                int i = lane * 32 + b;
                float* o6 = out + ((size_t)n * 100 + rank) * 6;
                o6[0] = g_box[n][i][0]; o6[1] = g_box[n][i][1];
                o6[2] = g_box[n][i][2]; o6[3] = g_box[n][i][3];
                o6[4] = g_lab[n][i];    o6[5] = g_sc[n][i];
            }
        }
    }
    __syncthreads();
    if (t == 0) g_candcnt[n] = 0u;
}

// ---------------- launch -----------------------------------------------------
extern "C" void kernel_launch(void* const* d_in, const int* in_sizes, int n_in,
                              void* d_out, int out_size) {
    const float* loc  = (const float*)d_in[0];
    const float* cls  = (const float*)d_in[1];
    const float* reg  = (const float*)d_in[2];
    const float* ctr  = (const float*)d_in[3];
    const float* info = (const float*)d_in[4];
    float* out = (float*)d_out;
    (void)in_sizes; (void)n_in; (void)out_size;

    cudaFuncSetAttribute(k_finish, cudaFuncAttributeMaxDynamicSharedMemorySize,
                         KPAD * 32 * 4);

    k_sample<<<dim3(SBLK, NIMG), 256>>>(cls, ctr);
    k_compact<<<dim3(15, 20, NIMG), 256>>>(cls, ctr);
    k_finish<<<NIMG, 1024, KPAD * 32 * 4>>>(cls, ctr, loc, reg, info, out);
}

// round 10
// speedup vs baseline: 2.3780x; 1.2609x over previous
#include <cuda_runtime.h>
#include <math.h>
#include <stdint.h>

// FCOS post-process, GB300 (sm_103a), round 10: 4 kernels.
// K1 hist: sampled 14-bit histogram via SMEM, sparse-merge to global
// K2 prep: per-block redundant t14 suffix-scan + xmin slice (fully parallel)
// K3 compact: max-gated 39MB scan, 4 classes/thread
// K4 finish: verify -> top-256 early-stop NMS -> out; inline guarded fallback;
//            re-zeros hist for next call.

#define NIMG 8
#define NCLS 80
#define PP   15200
#define CPE  (NCLS*PP)        // 1216000
#define TOPK 1000
#define KPAD 1024
#define SEL  256              // early-stop NMS window
#define SRT  512              // sort width (SEL + tie slack)
#define CAP  262144
#define CAP2 2048
#define NSAMP 960
#define NITEM (NSAMP*10)
#define SBLK 38
#define TARGET_S 100
#define C0 (-2.9444389791664403f)   // logit(0.05)
typedef unsigned long long ull;
typedef unsigned int uint;

// ---------------- device scratch (module-load zeroed; self-cleaning) ---------
__device__ ull  g_cand[NIMG][CAP];                   // 16 MB
__device__ uint g_hist14[NIMG][4096];
__device__ uint g_candcnt[NIMG];
__device__ uint g_T[NIMG];
__device__ float g_xmin[NIMG][PP];
__device__ float g_box [NIMG][KPAD][4];
__device__ float g_obox[NIMG][KPAD][4];
__device__ float g_area[NIMG][KPAD];
__device__ float g_lab [NIMG][KPAD];
__device__ float g_sc  [NIMG][KPAD];
__device__ uint g_validbits[NIMG][32];

__device__ __forceinline__ float sig_exact(float v) {
    return 1.0f / (1.0f + expf(-v));
}
__device__ __forceinline__ float score_apx(float x, float eyp) {
    return __frcp_rn(__fmul_rn(__fadd_rn(1.0f, __expf(-x)), eyp));
}
__device__ __forceinline__ float4 f4max(float4 a, float4 b) {
    return make_float4(fmaxf(a.x, b.x), fmaxf(a.y, b.y),
                      fmaxf(a.z, b.z), fmaxf(a.w, b.w));
}

// ---------------- K1: sampled hist via SMEM, sparse merge --------------------
__global__ __launch_bounds__(256) void k_hist(const float* __restrict__ cls,
                                              const float* __restrict__ ctr) {
    __shared__ uint sh[4096];
    int n = blockIdx.y;
    int t = threadIdx.x;
    for (int q = t; q < 4096; q += 256) sh[q] = 0u;
    __syncthreads();
    int item = blockIdx.x * 256 + t;
    if (item < NITEM) {
        int k  = item % NSAMP;
        int cb = item / NSAMP;
        int p = (k >> 4) * 253 + (k & 15);           // 60 runs of 16 points
        float eyp = __fadd_rn(1.0f, __expf(-ctr[(size_t)n * PP + p]));
        const float* base = cls + (size_t)n * CPE + p + (size_t)cb * 8 * PP;
        float xs[8];
#pragma unroll
        for (int i = 0; i < 8; i++) xs[i] = base[(size_t)i * PP];
#pragma unroll
        for (int i = 0; i < 8; i++) {
            if (xs[i] > C0) {
                uint b14 = __float_as_uint(score_apx(xs[i], eyp)) >> 18;
                if (b14 > 4095u) b14 = 4095u;
                if (b14) atomicAdd(&sh[b14], 1u);
            }
        }
    }
    __syncthreads();
    for (int q = t; q < 4096; q += 256) {
        uint v = sh[q];
        if (v) atomicAdd(&g_hist14[n][q], v);        // sparse: few hundred/block
    }
}

// ---------------- K2: per-block t14 + xmin slice (grid 60 x NIMG) ------------
__global__ __launch_bounds__(256) void k_prep(const float* __restrict__ ctr) {
    __shared__ uint ss[256];
    __shared__ float s_edge;
    int n = blockIdx.y;
    int t = threadIdx.x;
    uint loc[16]; uint s = 0;
#pragma unroll
    for (int i = 0; i < 16; i++) { loc[i] = g_hist14[n][t * 16 + i]; s += loc[i]; }
    ss[t] = s;
    __syncthreads();
    for (int off = 1; off < 256; off <<= 1) {        // suffix scan
        uint v = (t + off < 256) ? ss[t + off] : 0u;
        __syncthreads();
        ss[t] += v;
        __syncthreads();
    }
    uint mine = ss[t];
    uint above = (t + 1 < 256) ? ss[t + 1] : 0u;
    if (mine >= TARGET_S && above < TARGET_S) {      // unique crossing chunk
        uint cum = above, T = 1;
        for (int i = 15; i >= 0; i--) {
            cum += loc[i];
            if (cum >= TARGET_S) { T = (uint)(t * 16 + i); break; }
        }
        if (T < 1) T = 1;
        uint gate = (T > 2) ? T - 1 : 1u;
        g_T[n] = T;                                  // identical across blocks
        s_edge = __uint_as_float(gate << 18);
    }
    if (t == 0 && ss[0] < TARGET_S) {                // degenerate: keep all
        g_T[n] = 1;
        s_edge = __uint_as_float(1u << 18);
    }
    __syncthreads();
    float edge = s_edge;
    int p = blockIdx.x * 256 + t;
    if (p < PP) {
        float eyp = __fadd_rn(1.0f, __expf(-ctr[(size_t)n * PP + p]));
        float K = __fdividef(1.0f, __fmul_rn(edge, eyp)) - 1.0f;
        float xm = (K > 0.0f) ? (-__logf(K) - 0.002f) : 3.0e38f;
        g_xmin[n][p] = fmaxf(xm, C0);
    }
}

// ---------------- K3: max-gated full scan, 4 classes/thread ------------------
__global__ __launch_bounds__(256) void k_compact(const float* __restrict__ cls,
                                                 const float* __restrict__ ctr) {
    int n = blockIdx.z;
    int q = blockIdx.x * 256 + threadIdx.x;
    if (q >= PP / 4) return;
    int pb = q * 4;
    float4 xm4 = *(const float4*)&g_xmin[n][pb];
    float xm[4] = {xm4.x, xm4.y, xm4.z, xm4.w};
    int c0 = blockIdx.y * 4;
    const float* base = cls + (size_t)n * CPE + pb;
    float4 xv[4];
#pragma unroll
    for (int i = 0; i < 4; i++)
        xv[i] = *(const float4*)(base + (size_t)(c0 + i) * PP);
    float4 m4 = f4max(f4max(xv[0], xv[1]), f4max(xv[2], xv[3]));
    float mj[4] = {m4.x, m4.y, m4.z, m4.w};
#pragma unroll
    for (int j = 0; j < 4; j++) {
        if (mj[j] >= xm[j]) {                        // rare: some class passes
#pragma unroll
            for (int i = 0; i < 4; i++) {
                float x = (j == 0) ? xv[i].x : (j == 1) ? xv[i].y
                        : (j == 2) ? xv[i].z : xv[i].w;
                if (x >= xm[j]) {
                    float s = sig_exact(x);
                    if (s > 0.05f) {                 // exact candidacy
                        float y = ctr[(size_t)n * PP + pb + j];
                        float score = __fmul_rn(s, sig_exact(y));
                        uint sb = __float_as_uint(score);
                        uint idx = (uint)((pb + j) * NCLS + (c0 + i));
                        ull key = ((ull)sb << 32) | (ull)(0xFFFFFFFFu - idx);
                        uint pos = atomicAdd(&g_candcnt[n], 1u);
                        if (pos < CAP) g_cand[n][pos] = key;
                    }
                }
            }
        }
    }
}

// ---------------- decode helper ----------------------------------------------
__device__ __forceinline__ void decode_one(int n, ull key,
        const float* loc, const float* reg, const float* info,
        float4* box4, float4* ob4, float* area, float* lab, float* sc, bool* valid) {
    float x1 = 0, y1 = 0, x2 = 0, y2 = 0, labf = 0, score = 0;
    float ox1 = 0, oy1 = 0, ox2 = 0, oy2 = 0, ar = 0;
    bool vld = false;
    uint sb = (uint)(key >> 32);
    if (sb) {
        score = __uint_as_float(sb);
        uint i = 0xFFFFFFFFu - (uint)(key & 0xFFFFFFFFull);
        int p = (int)(i / NCLS);
        int c = (int)(i - (uint)(p * NCLS));
        labf = (float)(c + 1);
        float lx = loc[2 * p], ly = loc[2 * p + 1];
        float rl = reg[((size_t)(n * 4 + 0)) * PP + p];
        float rt = reg[((size_t)(n * 4 + 1)) * PP + p];
        float rr = reg[((size_t)(n * 4 + 2)) * PP + p];
        float rb = reg[((size_t)(n * 4 + 3)) * PP + p];
        float hm1 = __fsub_rn(info[2 * n + 0], 1.0f);
        float wm1 = __fsub_rn(info[2 * n + 1], 1.0f);
        x1 = fminf(fmaxf(__fsub_rn(lx, rl), 0.0f), wm1);
        y1 = fminf(fmaxf(__fsub_rn(ly, rt), 0.0f), hm1);
        x2 = fminf(fmaxf(__fadd_rn(lx, rr), 0.0f), wm1);
        y2 = fminf(fmaxf(__fadd_rn(ly, rb), 0.0f), hm1);
        vld = (score > 0.0f) &&
              (__fsub_rn(x2, x1) >= 0.0f) && (__fsub_rn(y2, y1) >= 0.0f);
        float off = __fmul_rn(labf, 1.0e5f);
        ox1 = __fadd_rn(x1, off); oy1 = __fadd_rn(y1, off);
        ox2 = __fadd_rn(x2, off); oy2 = __fadd_rn(y2, off);
        ar = __fmul_rn(fmaxf(__fsub_rn(ox2, ox1), 0.0f),
                       fmaxf(__fsub_rn(oy2, oy1), 0.0f));
    }
    *box4 = make_float4(x1, y1, x2, y2);
    *ob4  = make_float4(ox1, oy1, ox2, oy2);
    *area = ar; *lab = labf; *sc = score; *valid = vld;
}

__device__ __forceinline__ bool iou_sup(float4 bi, float ai, float4 bj, float aj) {
    float wv = fmaxf(__fsub_rn(fminf(bi.z, bj.z), fmaxf(bi.x, bj.x)), 0.0f);
    float hv = fmaxf(__fsub_rn(fminf(bi.w, bj.w), fmaxf(bi.y, bj.y)), 0.0f);
    float inter = __fmul_rn(wv, hv);
    float denom = __fadd_rn(__fsub_rn(__fadd_rn(ai, aj), inter), 1e-9f);
    return inter > __fmul_rn(0.6f, denom);           // iou > 0.6
}

// ---------------- full refine (slow path only) -------------------------------
__device__ void refine_core(int n, uint M,
                            const float* __restrict__ loc,
                            const float* __restrict__ reg,
                            const float* __restrict__ info,
                            ull* slist, uint* shist, uint* smisc) {
    int t = threadIdx.x;
    if (M <= CAP2) {
        for (int q = t; q < CAP2; q += 1024)
            slist[q] = (q < (int)M) ? g_cand[n][q] : 0ull;
        __syncthreads();
    } else {
        if (t == 0) { smisc[0] = 0u; smisc[1] = TOPK; smisc[2] = 0u; }
        __syncthreads();
        for (int lvl = 3; lvl >= 0; lvl--) {
            if (t < 256) shist[t] = 0u;
            __syncthreads();
            uint pfx = smisc[0];
            for (uint idx = t; idx < M; idx += 1024) {
                uint bits = (uint)(g_cand[n][idx] >> 32);
                bool cond = (lvl == 3) || ((bits >> ((lvl + 1) * 8)) == pfx);
                if (cond) atomicAdd(&shist[(bits >> (lvl * 8)) & 255u], 1u);
            }
            __syncthreads();
            if (t == 0) {
                uint cum = 0, rr = smisc[1]; int chosen = 0;
                for (int b = 255; b >= 0; b--) {
                    cum += shist[b];
                    if (cum >= rr) { chosen = b; smisc[1] = rr - (cum - shist[b]); break; }
                }
                smisc[0] = (smisc[0] << 8) | (uint)chosen;
            }
            __syncthreads();
        }
        uint sstar = smisc[0];
        for (int q = t; q < CAP2; q += 1024) slist[q] = 0ull;
        __syncthreads();
        for (uint idx = t; idx < M; idx += 1024) {
            ull key = g_cand[n][idx];
            if ((uint)(key >> 32) >= sstar) {
                uint pos = atomicAdd(&smisc[2], 1u);
                if (pos < CAP2) slist[pos] = key;
            }
        }
        __syncthreads();
    }
    for (int k2 = 2; k2 <= CAP2; k2 <<= 1) {
        for (int s2 = k2 >> 1; s2 >= 1; s2 >>= 1) {
            int i = ((t & ~(s2 - 1)) << 1) | (t & (s2 - 1));
            int l = i | s2;
            ull a = slist[i], b = slist[l];
            bool dir = ((i & k2) == 0);
            if ((a < b) == dir) { slist[i] = b; slist[l] = a; }
            __syncthreads();
        }
    }
    bool vld = false;
    float4 bx, ob; float ar, lb, sc;
    if (t < TOPK) {
        decode_one(n, slist[t], loc, reg, info, &bx, &ob, &ar, &lb, &sc, &vld);
    } else {
        bx = make_float4(0, 0, 0, 0); ob = bx; ar = 0; lb = 0; sc = 0;
    }
    *(float4*)&g_box[n][t][0] = bx;
    *(float4*)&g_obox[n][t][0] = ob;
    g_area[n][t] = ar; g_lab[n][t] = lb; g_sc[n][t] = sc;
    uint bal = __ballot_sync(0xffffffffu, vld);
    if ((t & 31) == 0) g_validbits[n][t >> 5] = bal;
}

// ---------------- K4: finish (fast top-256 path + inline full fallback) ------
__global__ __launch_bounds__(1024, 1) void k_finish(const float* __restrict__ cls,
                                                    const float* __restrict__ ctr,
                                                    const float* __restrict__ loc,
                                                    const float* __restrict__ reg,
                                                    const float* __restrict__ info,
                                                    float* __restrict__ out) {
    extern __shared__ uint smaskd[];                 // 128 KB (full path mask)
    __shared__ ull slist[CAP2];                      // 16 KB (fast uses [0,SRT))
    __shared__ uint shist[256];
    __shared__ uint smisc[8];
    __shared__ float4 sbox[SEL], sob[SEL];
    __shared__ float sar[SEL], slb[SEL], ssc[SEL];
    __shared__ uint svalid[8];
    __shared__ uint smask[SEL * 8];                  // 8 KB
    __shared__ int s_path;                           // 0 fast-ok, 1 rebuild, 2 full-nms
    __shared__ float4 sobF[KPAD];
    __shared__ float sarF[KPAD], slbF[KPAD];
    int n = blockIdx.x;
    int t = threadIdx.x;
    int lane = t & 31;
    if (t < 600) out[(size_t)n * 600 + t] = 0.0f;
    for (int q = t; q < 4096; q += 1024) g_hist14[n][q] = 0u;   // reset for next call
    uint attempted = g_candcnt[n];
    uint M = attempted > CAP ? CAP : attempted;
    if (t == 0) { smisc[3] = 0u; s_path = 0; }
    __syncthreads();
    // verify completeness to depth >= TOPK
    {
        uint Vb = g_T[n] << 18;
        uint local = 0;
        for (uint idx = t; idx < M; idx += 1024)
            if ((uint)(g_cand[n][idx] >> 32) >= Vb) local++;
        if (local) atomicAdd(&smisc[3], local);
    }
    __syncthreads();
    if (smisc[3] < TOPK || attempted > CAP) {
        if (t == 0) s_path = 1;
    }
    __syncthreads();
    if (s_path == 0) {
        // ---- fast path: radix select exact rank-SEL threshold ----
        if (t == 0) { smisc[0] = 0u; smisc[1] = SEL; smisc[2] = 0u; }
        __syncthreads();
        for (int lvl = 3; lvl >= 0; lvl--) {
            if (t < 256) shist[t] = 0u;
            __syncthreads();
            uint pfx = smisc[0];
            for (uint idx = t; idx < M; idx += 1024) {
                uint bits = (uint)(g_cand[n][idx] >> 32);
                bool cond = (lvl == 3) || ((bits >> ((lvl + 1) * 8)) == pfx);
                if (cond) atomicAdd(&shist[(bits >> (lvl * 8)) & 255u], 1u);
            }
            __syncthreads();
            if (t == 0) {
                uint cum = 0, rr = smisc[1]; int chosen = 0;
                for (int b = 255; b >= 0; b--) {
                    cum += shist[b];
                    if (cum >= rr) { chosen = b; smisc[1] = rr - (cum - shist[b]); break; }
                }
                smisc[0] = (smisc[0] << 8) | (uint)chosen;
            }
            __syncthreads();
        }
        uint sstar = smisc[0];
        if (t < SRT) slist[t] = 0ull;
        __syncthreads();
        for (uint idx = t; idx < M; idx += 1024) {
            ull key = g_cand[n][idx];
            if ((uint)(key >> 32) >= sstar) {
                uint pos = atomicAdd(&smisc[2], 1u);
                if (pos < SRT) slist[pos] = key;
            }
        }
        __syncthreads();
        if (smisc[2] > SRT) {                        // absurd tie explosion
            if (t == 0) s_path = 2;
        }
        __syncthreads();
        if (s_path == 0) {
            for (int k2 = 2; k2 <= SRT; k2 <<= 1) {
                for (int s2 = k2 >> 1; s2 >= 1; s2 >>= 1) {
                    if (t < SRT / 2) {
                        int i = ((t & ~(s2 - 1)) << 1) | (t & (s2 - 1));
                        int l = i | s2;
                        ull a = slist[i], b = slist[l];
                        bool dir = ((i & k2) == 0);
                        if ((a < b) == dir) { slist[i] = b; slist[l] = a; }
                    }
                    __syncthreads();
                }
            }
            if (t < SEL) {
                bool vld;
                decode_one(n, slist[t], loc, reg, info,
                           &sbox[t], &sob[t], &sar[t], &slb[t], &ssc[t], &vld);
                uint bal = __ballot_sync(0xffffffffu, vld);
                if ((t & 31) == 0) svalid[t >> 5] = bal;
            }
            __syncthreads();
            {
                int warp = t >> 5;
#pragma unroll
                for (int r = 0; r < 8; r++) {
                    int i = warp * 8 + r;
                    float4 bi = sob[i];
                    float ai = sar[i];
                    float li = slb[i];
#pragma unroll
                    for (int wd = 0; wd < 8; wd++) {
                        int j = wd * 32 + lane;
                        bool sup = false;
                        if (j > i && slb[j] == li)
                            sup = iou_sup(bi, ai, sob[j], sar[j]);
                        uint bits = __ballot_sync(0xffffffffu, sup);
                        if (lane == 0) smask[i * 8 + wd] = bits;
                    }
                }
            }
            __syncthreads();
            if (t < 32) {
                uint validw = (lane < 8) ? svalid[lane] : 0u;
                uint removew = 0u;
                for (int g = 0; g < 8; g++) {
                    uint cur_sup = __shfl_sync(0xffffffffu, removew, g);
                    uint cur_val = __shfl_sync(0xffffffffu, validw, g);
                    uint rowv[32], diag[32];
#pragma unroll
                    for (int b = 0; b < 32; b++) {
                        rowv[b] = (lane < 8) ? smask[(g * 32 + b) * 8 + lane] : 0u;
                        diag[b] = smask[(g * 32 + b) * 8 + g];
                    }
#pragma unroll
                    for (int b = 0; b < 32; b++) {
                        bool alive = ((cur_val >> b) & 1u) && !((cur_sup >> b) & 1u);
                        if (alive) { removew |= rowv[b]; cur_sup |= diag[b]; }
                    }
                }
                uint keepw = validw & ~removew;
                int kv = __popc(keepw);
                int tot = kv;
#pragma unroll
                for (int o = 1; o < 32; o <<= 1)     // full-warp: uniform tot
                    tot += __shfl_xor_sync(0xffffffffu, tot, o);
                if (tot >= 100) {
                    int inc = kv;
                    for (int o = 1; o < 32; o <<= 1) {
                        int v = __shfl_up_sync(0xffffffffu, inc, o);
                        if (lane >= o) inc += v;
                    }
                    int basei = inc - kv;
                    uint m = keepw;
                    while (m) {
                        int b = __ffs(m) - 1;
                        m &= m - 1;
                        int rank = basei + __popc(keepw & ((1u << b) - 1u));
                        if (rank < 100) {
                            int i = lane * 32 + b;
                            float* o6 = out + ((size_t)n * 100 + rank) * 6;
                            float4 bx = sbox[i];
                            o6[0] = bx.x; o6[1] = bx.y; o6[2] = bx.z; o6[3] = bx.w;
                            o6[4] = slb[i]; o6[5] = ssc[i];
                        }
                    }
                } else if (lane == 0) {
                    s_path = 2;                      // need full-width NMS
                }
            }
            __syncthreads();
        }
    }
    if (s_path == 0) {
        if (t == 0) g_candcnt[n] = 0u;
        return;                                      // fast path done
    }
    // ================= slow path (guarded; never in practice) =================
    if (s_path == 1) {                               // exact candidate rebuild
        if (t < 256) shist[t] = 0u;
        if (t == 0) g_candcnt[n] = 0u;
        __syncthreads();
        const float* clsn = cls + (size_t)n * CPE;
        const float* ctrn = ctr + (size_t)n * PP;
        for (int j = t; j < CPE; j += 1024) {
            int p = j % PP;
            float s = sig_exact(clsn[j]);
            if (s > 0.05f) {
                uint b = __float_as_uint(__fmul_rn(s, sig_exact(ctrn[p]))) >> 24;
                if (b) atomicAdd(&shist[b], 1u);
            }
        }
        __syncthreads();
        if (t == 0) {
            uint cum = 0, b1 = 1;
            for (int b = 255; b >= 1; b--) {
                cum += shist[b];
                if (cum >= TOPK) { b1 = (uint)b; break; }
            }
            smisc[4] = b1;
        }
        __syncthreads();
        uint b1 = smisc[4];
        for (int j = t; j < CPE; j += 1024) {
            int p = j % PP;
            float s = sig_exact(clsn[j]);
            if (s > 0.05f) {
                float score = __fmul_rn(s, sig_exact(ctrn[p]));
                uint sb = __float_as_uint(score);
                if ((sb >> 24) >= b1) {
                    int c = j / PP;
                    uint i = (uint)(p * NCLS + c);
                    ull key = ((ull)sb << 32) | (ull)(0xFFFFFFFFu - i);
                    uint pos = atomicAdd(&g_candcnt[n], 1u);
                    if (pos < CAP) g_cand[n][pos] = key;
                }
            }
        }
        __syncthreads();
        attempted = g_candcnt[n];
        M = attempted > CAP ? CAP : attempted;
    }
    refine_core(n, M, loc, reg, info, slist, shist, smisc);
    __syncthreads();
    if (t < 600) out[(size_t)n * 600 + t] = 0.0f;    // re-zero (fast may have run)
    sobF[t] = *(float4*)&g_obox[n][t][0];
    sarF[t] = g_area[n][t];
    slbF[t] = g_lab[n][t];
    __syncthreads();
    int warp = t >> 5;
    for (int r = 0; r < 32; r++) {
        int i = r * 32 + warp;
        float4 bi = sobF[i];
        float ai = sarF[i];
        float li = slbF[i];
        uint myword = 0u;
        for (int w = r; w < 32; w++) {
            int j = w * 32 + lane;
            bool sup = false;
            if (j > i && slbF[j] == li)
                sup = iou_sup(bi, ai, sobF[j], sarF[j]);
            uint bits = __ballot_sync(0xffffffffu, sup);
            if (lane == w) myword = bits;
        }
        smaskd[i * 32 + lane] = (lane >= r) ? myword : 0u;
    }
    __syncthreads();
    if (t < 32) {
        uint validw = g_validbits[n][lane];
        uint removew = 0u;
        for (int g = 0; g < 32; g++) {
            uint cur_sup = __shfl_sync(0xffffffffu, removew, g);
            uint cur_val = __shfl_sync(0xffffffffu, validw, g);
            uint rowv[32], diag[32];
#pragma unroll
            for (int b = 0; b < 32; b++) {
                rowv[b] = smaskd[(g * 32 + b) * 32 + lane];
                diag[b] = smaskd[(g * 32 + b) * 32 + g];
            }
#pragma unroll
            for (int b = 0; b < 32; b++) {
                bool alive = ((cur_val >> b) & 1u) && !((cur_sup >> b) & 1u);
                if (alive) { removew |= rowv[b]; cur_sup |= diag[b]; }
            }
        }
        uint keepw = validw & ~removew;
        int cnt = __popc(keepw);
        int inc = cnt;
        for (int o = 1; o < 32; o <<= 1) {
            int v = __shfl_up_sync(0xffffffffu, inc, o);
            if (lane >= o) inc += v;
        }
        int basei = inc - cnt;
        uint m = keepw;
        while (m) {
            int b = __ffs(m) - 1;
            m &= m - 1;
            int rank = basei + __popc(keepw & ((1u << b) - 1u));
            if (rank < 100) {
                int i = lane * 32 + b;
                float* o6 = out + ((size_t)n * 100 + rank) * 6;
                o6[0] = g_box[n][i][0]; o6[1] = g_box[n][i][1];
                o6[2] = g_box[n][i][2]; o6[3] = g_box[n][i][3];
                o6[4] = g_lab[n][i];    o6[5] = g_sc[n][i];
            }
        }
    }
    __syncthreads();
    if (t == 0) g_candcnt[n] = 0u;
}

// ---------------- launch -----------------------------------------------------
extern "C" void kernel_launch(void* const* d_in, const int* in_sizes, int n_in,
                              void* d_out, int out_size) {
    const float* loc  = (const float*)d_in[0];
    const float* cls  = (const float*)d_in[1];
    const float* reg  = (const float*)d_in[2];
    const float* ctr  = (const float*)d_in[3];
    const float* info = (const float*)d_in[4];
    float* out = (float*)d_out;
    (void)in_sizes; (void)n_in; (void)out_size;

    cudaFuncSetAttribute(k_finish, cudaFuncAttributeMaxDynamicSharedMemorySize,
                         KPAD * 32 * 4);

    k_hist<<<dim3(SBLK, NIMG), 256>>>(cls, ctr);
    k_prep<<<dim3(60, NIMG), 256>>>(ctr);
    k_compact<<<dim3(15, 20, NIMG), 256>>>(cls, ctr);
    k_finish<<<NIMG, 1024, KPAD * 32 * 4>>>(cls, ctr, loc, reg, info, out);
}

// round 11
// speedup vs baseline: 3.1300x; 1.3162x over previous
#include <cuda_runtime.h>
#include <math.h>
#include <stdint.h>

// FCOS post-process, GB300 (sm_103a), round 11.
// = round 10 + parallel suffix-scan byte-pick in radix select (kills the
//   serial t==0 histogram walk that dominated k_finish at 45.9us).

#define NIMG 8
#define NCLS 80
#define PP   15200
#define CPE  (NCLS*PP)        // 1216000
#define TOPK 1000
#define KPAD 1024
#define SEL  256              // early-stop NMS window
#define SRT  512              // sort width (SEL + tie slack)
#define CAP  262144
#define CAP2 2048
#define NSAMP 960
#define NITEM (NSAMP*10)
#define SBLK 38
#define TARGET_S 100
#define C0 (-2.9444389791664403f)   // logit(0.05)
typedef unsigned long long ull;
typedef unsigned int uint;

// ---------------- device scratch (module-load zeroed; self-cleaning) ---------
__device__ ull  g_cand[NIMG][CAP];                   // 16 MB
__device__ uint g_hist14[NIMG][4096];
__device__ uint g_candcnt[NIMG];
__device__ uint g_T[NIMG];
__device__ float g_xmin[NIMG][PP];
__device__ float g_box [NIMG][KPAD][4];
__device__ float g_obox[NIMG][KPAD][4];
__device__ float g_area[NIMG][KPAD];
__device__ float g_lab [NIMG][KPAD];
__device__ float g_sc  [NIMG][KPAD];
__device__ uint g_validbits[NIMG][32];

__device__ __forceinline__ float sig_exact(float v) {
    return 1.0f / (1.0f + expf(-v));
}
__device__ __forceinline__ float score_apx(float x, float eyp) {
    return __frcp_rn(__fmul_rn(__fadd_rn(1.0f, __expf(-x)), eyp));
}
__device__ __forceinline__ float4 f4max(float4 a, float4 b) {
    return make_float4(fmaxf(a.x, b.x), fmaxf(a.y, b.y),
                      fmaxf(a.z, b.z), fmaxf(a.w, b.w));
}

// Parallel radix-select over key high-32 bits stored in g_cand[n][0..M).
// On return smisc[0] holds the exact scorebits threshold for rank `rank`.
// Requires blockDim >= 256; shist is uint[256] shared; smisc[0..1] shared.
__device__ void radix_select(int n, uint M, uint rank, uint* shist, uint* smisc) {
    int t = threadIdx.x;
    int bdim = blockDim.x;
    if (t == 0) { smisc[0] = 0u; smisc[1] = rank; }
    __syncthreads();
    for (int lvl = 3; lvl >= 0; lvl--) {
        if (t < 256) shist[t] = 0u;
        __syncthreads();
        uint pfx = smisc[0];
        for (uint idx = t; idx < M; idx += bdim) {
            uint bits = (uint)(g_cand[n][idx] >> 32);
            bool cond = (lvl == 3) || ((bits >> ((lvl + 1) * 8)) == pfx);
            if (cond) atomicAdd(&shist[(bits >> (lvl * 8)) & 255u], 1u);
        }
        __syncthreads();
        // in-place suffix scan of shist (parallel byte pick)
        for (int off = 1; off < 256; off <<= 1) {
            uint v = 0;
            if (t < 256 && t + off < 256) v = shist[t + off];
            __syncthreads();
            if (t < 256) shist[t] += v;
            __syncthreads();
        }
        if (t < 256) {
            uint rr = smisc[1];
            uint mine = shist[t];
            uint above = (t < 255) ? shist[t + 1] : 0u;
            if (mine >= rr && above < rr) {          // unique crossing byte
                smisc[1] = rr - above;
                smisc[0] = (smisc[0] << 8) | (uint)t;
            }
        }
        __syncthreads();
    }
}

// ---------------- K1: sampled hist via SMEM, sparse merge --------------------
__global__ __launch_bounds__(256) void k_hist(const float* __restrict__ cls,
                                              const float* __restrict__ ctr) {
    __shared__ uint sh[4096];
    int n = blockIdx.y;
    int t = threadIdx.x;
    for (int q = t; q < 4096; q += 256) sh[q] = 0u;
    __syncthreads();
    int item = blockIdx.x * 256 + t;
    if (item < NITEM) {
        int k  = item % NSAMP;
        int cb = item / NSAMP;
        int p = (k >> 4) * 253 + (k & 15);           // 60 runs of 16 points
        float eyp = __fadd_rn(1.0f, __expf(-ctr[(size_t)n * PP + p]));
        const float* base = cls + (size_t)n * CPE + p + (size_t)cb * 8 * PP;
        float xs[8];
#pragma unroll
        for (int i = 0; i < 8; i++) xs[i] = base[(size_t)i * PP];
#pragma unroll
        for (int i = 0; i < 8; i++) {
            if (xs[i] > C0) {
                uint b14 = __float_as_uint(score_apx(xs[i], eyp)) >> 18;
                if (b14 > 4095u) b14 = 4095u;
                if (b14) atomicAdd(&sh[b14], 1u);
            }
        }
    }
    __syncthreads();
    for (int q = t; q < 4096; q += 256) {
        uint v = sh[q];
        if (v) atomicAdd(&g_hist14[n][q], v);        // sparse: few hundred/block
    }
}

// ---------------- K2: per-block t14 + xmin slice (grid 60 x NIMG) ------------
__global__ __launch_bounds__(256) void k_prep(const float* __restrict__ ctr) {
    __shared__ uint ss[256];
    __shared__ float s_edge;
    int n = blockIdx.y;
    int t = threadIdx.x;
    uint loc[16]; uint s = 0;
#pragma unroll
    for (int i = 0; i < 16; i++) { loc[i] = g_hist14[n][t * 16 + i]; s += loc[i]; }
    ss[t] = s;
    __syncthreads();
    for (int off = 1; off < 256; off <<= 1) {        // suffix scan
        uint v = (t + off < 256) ? ss[t + off] : 0u;
        __syncthreads();
        ss[t] += v;
        __syncthreads();
    }
    uint mine = ss[t];
    uint above = (t + 1 < 256) ? ss[t + 1] : 0u;
    if (mine >= TARGET_S && above < TARGET_S) {      // unique crossing chunk
        uint cum = above, T = 1;
        for (int i = 15; i >= 0; i--) {
            cum += loc[i];
            if (cum >= TARGET_S) { T = (uint)(t * 16 + i); break; }
        }
        if (T < 1) T = 1;
        uint gate = (T > 2) ? T - 1 : 1u;
        g_T[n] = T;                                  // identical across blocks
        s_edge = __uint_as_float(gate << 18);
    }
    if (t == 0 && ss[0] < TARGET_S) {                // degenerate: keep all
        g_T[n] = 1;
        s_edge = __uint_as_float(1u << 18);
    }
    __syncthreads();
    float edge = s_edge;
    int p = blockIdx.x * 256 + t;
    if (p < PP) {
        float eyp = __fadd_rn(1.0f, __expf(-ctr[(size_t)n * PP + p]));
        float K = __fdividef(1.0f, __fmul_rn(edge, eyp)) - 1.0f;
        float xm = (K > 0.0f) ? (-__logf(K) - 0.002f) : 3.0e38f;
        g_xmin[n][p] = fmaxf(xm, C0);
    }
}

// ---------------- K3: max-gated full scan, 4 classes/thread ------------------
__global__ __launch_bounds__(256) void k_compact(const float* __restrict__ cls,
                                                 const float* __restrict__ ctr) {
    int n = blockIdx.z;
    int q = blockIdx.x * 256 + threadIdx.x;
    if (q >= PP / 4) return;
    int pb = q * 4;
    float4 xm4 = *(const float4*)&g_xmin[n][pb];
    float xm[4] = {xm4.x, xm4.y, xm4.z, xm4.w};
    int c0 = blockIdx.y * 4;
    const float* base = cls + (size_t)n * CPE + pb;
    float4 xv[4];
#pragma unroll
    for (int i = 0; i < 4; i++)
        xv[i] = *(const float4*)(base + (size_t)(c0 + i) * PP);
    float4 m4 = f4max(f4max(xv[0], xv[1]), f4max(xv[2], xv[3]));
    float mj[4] = {m4.x, m4.y, m4.z, m4.w};
#pragma unroll
    for (int j = 0; j < 4; j++) {
        if (mj[j] >= xm[j]) {                        // rare: some class passes
#pragma unroll
            for (int i = 0; i < 4; i++) {
                float x = (j == 0) ? xv[i].x : (j == 1) ? xv[i].y
                        : (j == 2) ? xv[i].z : xv[i].w;
                if (x >= xm[j]) {
                    float s = sig_exact(x);
                    if (s > 0.05f) {                 // exact candidacy
                        float y = ctr[(size_t)n * PP + pb + j];
                        float score = __fmul_rn(s, sig_exact(y));
                        uint sb = __float_as_uint(score);
                        uint idx = (uint)((pb + j) * NCLS + (c0 + i));
                        ull key = ((ull)sb << 32) | (ull)(0xFFFFFFFFu - idx);
                        uint pos = atomicAdd(&g_candcnt[n], 1u);
                        if (pos < CAP) g_cand[n][pos] = key;
                    }
                }
            }
        }
    }
}

// ---------------- decode helper ----------------------------------------------
__device__ __forceinline__ void decode_one(int n, ull key,
        const float* loc, const float* reg, const float* info,
        float4* box4, float4* ob4, float* area, float* lab, float* sc, bool* valid) {
    float x1 = 0, y1 = 0, x2 = 0, y2 = 0, labf = 0, score = 0;
    float ox1 = 0, oy1 = 0, ox2 = 0, oy2 = 0, ar = 0;
    bool vld = false;
    uint sb = (uint)(key >> 32);
    if (sb) {
        score = __uint_as_float(sb);
        uint i = 0xFFFFFFFFu - (uint)(key & 0xFFFFFFFFull);
        int p = (int)(i / NCLS);
        int c = (int)(i - (uint)(p * NCLS));
        labf = (float)(c + 1);
        float lx = loc[2 * p], ly = loc[2 * p + 1];
        float rl = reg[((size_t)(n * 4 + 0)) * PP + p];
        float rt = reg[((size_t)(n * 4 + 1)) * PP + p];
        float rr = reg[((size_t)(n * 4 + 2)) * PP + p];
        float rb = reg[((size_t)(n * 4 + 3)) * PP + p];
        float hm1 = __fsub_rn(info[2 * n + 0], 1.0f);
        float wm1 = __fsub_rn(info[2 * n + 1], 1.0f);
        x1 = fminf(fmaxf(__fsub_rn(lx, rl), 0.0f), wm1);
        y1 = fminf(fmaxf(__fsub_rn(ly, rt), 0.0f), hm1);
        x2 = fminf(fmaxf(__fadd_rn(lx, rr), 0.0f), wm1);
        y2 = fminf(fmaxf(__fadd_rn(ly, rb), 0.0f), hm1);
        vld = (score > 0.0f) &&
              (__fsub_rn(x2, x1) >= 0.0f) && (__fsub_rn(y2, y1) >= 0.0f);
        float off = __fmul_rn(labf, 1.0e5f);
        ox1 = __fadd_rn(x1, off); oy1 = __fadd_rn(y1, off);
        ox2 = __fadd_rn(x2, off); oy2 = __fadd_rn(y2, off);
        ar = __fmul_rn(fmaxf(__fsub_rn(ox2, ox1), 0.0f),
                       fmaxf(__fsub_rn(oy2, oy1), 0.0f));
    }
    *box4 = make_float4(x1, y1, x2, y2);
    *ob4  = make_float4(ox1, oy1, ox2, oy2);
    *area = ar; *lab = labf; *sc = score; *valid = vld;
}

__device__ __forceinline__ bool iou_sup(float4 bi, float ai, float4 bj, float aj) {
    float wv = fmaxf(__fsub_rn(fminf(bi.z, bj.z), fmaxf(bi.x, bj.x)), 0.0f);
    float hv = fmaxf(__fsub_rn(fminf(bi.w, bj.w), fmaxf(bi.y, bj.y)), 0.0f);
    float inter = __fmul_rn(wv, hv);
    float denom = __fadd_rn(__fsub_rn(__fadd_rn(ai, aj), inter), 1e-9f);
    return inter > __fmul_rn(0.6f, denom);           // iou > 0.6
}

// ---------------- full refine (slow path only) -------------------------------
__device__ void refine_core(int n, uint M,
                            const float* __restrict__ loc,
                            const float* __restrict__ reg,
                            const float* __restrict__ info,
                            ull* slist, uint* shist, uint* smisc) {
    int t = threadIdx.x;
    if (M <= CAP2) {
        for (int q = t; q < CAP2; q += 1024)
            slist[q] = (q < (int)M) ? g_cand[n][q] : 0ull;
        __syncthreads();
    } else {
        radix_select(n, M, TOPK, shist, smisc);
        uint sstar = smisc[0];
        if (t == 0) smisc[2] = 0u;
        for (int q = t; q < CAP2; q += 1024) slist[q] = 0ull;
        __syncthreads();
        for (uint idx = t; idx < M; idx += 1024) {
            ull key = g_cand[n][idx];
            if ((uint)(key >> 32) >= sstar) {
                uint pos = atomicAdd(&smisc[2], 1u);
                if (pos < CAP2) slist[pos] = key;
            }
        }
        __syncthreads();
    }
    for (int k2 = 2; k2 <= CAP2; k2 <<= 1) {
        for (int s2 = k2 >> 1; s2 >= 1; s2 >>= 1) {
            int i = ((t & ~(s2 - 1)) << 1) | (t & (s2 - 1));
            int l = i | s2;
            ull a = slist[i], b = slist[l];
            bool dir = ((i & k2) == 0);
            if ((a < b) == dir) { slist[i] = b; slist[l] = a; }
            __syncthreads();
        }
    }
    bool vld = false;
    float4 bx, ob; float ar, lb, sc;
    if (t < TOPK) {
        decode_one(n, slist[t], loc, reg, info, &bx, &ob, &ar, &lb, &sc, &vld);
    } else {
        bx = make_float4(0, 0, 0, 0); ob = bx; ar = 0; lb = 0; sc = 0;
    }
    *(float4*)&g_box[n][t][0] = bx;
    *(float4*)&g_obox[n][t][0] = ob;
    g_area[n][t] = ar; g_lab[n][t] = lb; g_sc[n][t] = sc;
    uint bal = __ballot_sync(0xffffffffu, vld);
    if ((t & 31) == 0) g_validbits[n][t >> 5] = bal;
}

// ---------------- K4: finish (fast top-256 path + inline full fallback) ------
__global__ __launch_bounds__(1024, 1) void k_finish(const float* __restrict__ cls,
                                                    const float* __restrict__ ctr,
                                                    const float* __restrict__ loc,
                                                    const float* __restrict__ reg,
                                                    const float* __restrict__ info,
                                                    float* __restrict__ out) {
    extern __shared__ uint smaskd[];                 // 128 KB (full path mask)
    __shared__ ull slist[CAP2];                      // 16 KB (fast uses [0,SRT))
    __shared__ uint shist[256];
    __shared__ uint smisc[8];
    __shared__ float4 sbox[SEL], sob[SEL];
    __shared__ float sar[SEL], slb[SEL], ssc[SEL];
    __shared__ uint svalid[8];
    __shared__ uint smask[SEL * 8];                  // 8 KB
    __shared__ int s_path;                           // 0 fast-ok, 1 rebuild, 2 full-nms
    __shared__ float4 sobF[KPAD];
    __shared__ float sarF[KPAD], slbF[KPAD];
    int n = blockIdx.x;
    int t = threadIdx.x;
    int lane = t & 31;
    if (t < 600) out[(size_t)n * 600 + t] = 0.0f;
    for (int q = t; q < 4096; q += 1024) g_hist14[n][q] = 0u;   // reset for next call
    uint attempted = g_candcnt[n];
    uint M = attempted > CAP ? CAP : attempted;
    if (t == 0) { smisc[3] = 0u; s_path = 0; }
    __syncthreads();
    // verify completeness to depth >= TOPK
    {
        uint Vb = g_T[n] << 18;
        uint local = 0;
        for (uint idx = t; idx < M; idx += 1024)
            if ((uint)(g_cand[n][idx] >> 32) >= Vb) local++;
        if (local) atomicAdd(&smisc[3], local);
    }
    __syncthreads();
    if (smisc[3] < TOPK || attempted > CAP) {
        if (t == 0) s_path = 1;
    }
    __syncthreads();
    if (s_path == 0) {
        // ---- fast path: radix select exact rank-SEL threshold (parallel) ----
        radix_select(n, M, SEL, shist, smisc);
        uint sstar = smisc[0];
        if (t == 0) smisc[2] = 0u;
        if (t < SRT) slist[t] = 0ull;
        __syncthreads();
        for (uint idx = t; idx < M; idx += 1024) {
            ull key = g_cand[n][idx];
            if ((uint)(key >> 32) >= sstar) {
                uint pos = atomicAdd(&smisc[2], 1u);
                if (pos < SRT) slist[pos] = key;
            }
        }
        __syncthreads();
        if (smisc[2] > SRT) {                        // absurd tie explosion
            if (t == 0) s_path = 2;
        }
        __syncthreads();
        if (s_path == 0) {
            for (int k2 = 2; k2 <= SRT; k2 <<= 1) {
                for (int s2 = k2 >> 1; s2 >= 1; s2 >>= 1) {
                    if (t < SRT / 2) {
                        int i = ((t & ~(s2 - 1)) << 1) | (t & (s2 - 1));
                        int l = i | s2;
                        ull a = slist[i], b = slist[l];
                        bool dir = ((i & k2) == 0);
                        if ((a < b) == dir) { slist[i] = b; slist[l] = a; }
                    }
                    __syncthreads();
                }
            }
            if (t < SEL) {
                bool vld;
                decode_one(n, slist[t], loc, reg, info,
                           &sbox[t], &sob[t], &sar[t], &slb[t], &ssc[t], &vld);
                uint bal = __ballot_sync(0xffffffffu, vld);
                if ((t & 31) == 0) svalid[t >> 5] = bal;
            }
            __syncthreads();
            {
                int warp = t >> 5;
#pragma unroll
                for (int r = 0; r < 8; r++) {
                    int i = warp * 8 + r;
                    float4 bi = sob[i];
                    float ai = sar[i];
                    float li = slb[i];
#pragma unroll
                    for (int wd = 0; wd < 8; wd++) {
                        int j = wd * 32 + lane;
                        bool sup = false;
                        if (j > i && slb[j] == li)
                            sup = iou_sup(bi, ai, sob[j], sar[j]);
                        uint bits = __ballot_sync(0xffffffffu, sup);
                        if (lane == 0) smask[i * 8 + wd] = bits;
                    }
                }
            }
            __syncthreads();
            if (t < 32) {
                uint validw = (lane < 8) ? svalid[lane] : 0u;
                uint removew = 0u;
                for (int g = 0; g < 8; g++) {
                    uint cur_sup = __shfl_sync(0xffffffffu, removew, g);
                    uint cur_val = __shfl_sync(0xffffffffu, validw, g);
                    uint rowv[32], diag[32];
#pragma unroll
                    for (int b = 0; b < 32; b++) {
                        rowv[b] = (lane < 8) ? smask[(g * 32 + b) * 8 + lane] : 0u;
                        diag[b] = smask[(g * 32 + b) * 8 + g];
                    }
#pragma unroll
                    for (int b = 0; b < 32; b++) {
                        bool alive = ((cur_val >> b) & 1u) && !((cur_sup >> b) & 1u);
                        if (alive) { removew |= rowv[b]; cur_sup |= diag[b]; }
                    }
                }
                uint keepw = validw & ~removew;
                int kv = __popc(keepw);
                int tot = kv;
#pragma unroll
                for (int o = 1; o < 32; o <<= 1)     // full-warp: uniform tot
                    tot += __shfl_xor_sync(0xffffffffu, tot, o);
                if (tot >= 100) {
                    int inc = kv;
                    for (int o = 1; o < 32; o <<= 1) {
                        int v = __shfl_up_sync(0xffffffffu, inc, o);
                        if (lane >= o) inc += v;
                    }
                    int basei = inc - kv;
                    uint m = keepw;
                    while (m) {
                        int b = __ffs(m) - 1;
                        m &= m - 1;
                        int rank = basei + __popc(keepw & ((1u << b) - 1u));
                        if (rank < 100) {
                            int i = lane * 32 + b;
                            float* o6 = out + ((size_t)n * 100 + rank) * 6;
                            float4 bx = sbox[i];
                            o6[0] = bx.x; o6[1] = bx.y; o6[2] = bx.z; o6[3] = bx.w;
                            o6[4] = slb[i]; o6[5] = ssc[i];
                        }
                    }
                } else if (lane == 0) {
                    s_path = 2;                      // need full-width NMS
                }
            }
            __syncthreads();
        }
    }
    if (s_path == 0) {
        if (t == 0) g_candcnt[n] = 0u;
        return;                                      // fast path done
    }
    // ================= slow path (guarded; never in practice) =================
    if (s_path == 1) {                               // exact candidate rebuild
        if (t < 256) shist[t] = 0u;
        if (t == 0) g_candcnt[n] = 0u;
        __syncthreads();
        const float* clsn = cls + (size_t)n * CPE;
        const float* ctrn = ctr + (size_t)n * PP;
        for (int j = t; j < CPE; j += 1024) {
            int p = j % PP;
            float s = sig_exact(clsn[j]);
            if (s > 0.05f) {
                uint b = __float_as_uint(__fmul_rn(s, sig_exact(ctrn[p]))) >> 24;
                if (b) atomicAdd(&shist[b], 1u);
            }
        }
        __syncthreads();
        if (t == 0) {
            uint cum = 0, b1 = 1;
            for (int b = 255; b >= 1; b--) {
                cum += shist[b];
                if (cum >= TOPK) { b1 = (uint)b; break; }
            }
            smisc[4] = b1;
        }
        __syncthreads();
        uint b1 = smisc[4];
        for (int j = t; j < CPE; j += 1024) {
            int p = j % PP;
            float s = sig_exact(clsn[j]);
            if (s > 0.05f) {
                float score = __fmul_rn(s, sig_exact(ctrn[p]));
                uint sb = __float_as_uint(score);
                if ((sb >> 24) >= b1) {
                    int c = j / PP;
                    uint i = (uint)(p * NCLS + c);
                    ull key = ((ull)sb << 32) | (ull)(0xFFFFFFFFu - i);
                    uint pos = atomicAdd(&g_candcnt[n], 1u);
                    if (pos < CAP) g_cand[n][pos] = key;
                }
            }
        }
        __syncthreads();
        attempted = g_candcnt[n];
        M = attempted > CAP ? CAP : attempted;
    }
    refine_core(n, M, loc, reg, info, slist, shist, smisc);
    __syncthreads();
    if (t < 600) out[(size_t)n * 600 + t] = 0.0f;    // re-zero (fast may have run)
    sobF[t] = *(float4*)&g_obox[n][t][0];
    sarF[t] = g_area[n][t];
    slbF[t] = g_lab[n][t];
    __syncthreads();
    int warp = t >> 5;
    for (int r = 0; r < 32; r++) {
        int i = r * 32 + warp;
        float4 bi = sobF[i];
        float ai = sarF[i];
        float li = slbF[i];
        uint myword = 0u;
        for (int w = r; w < 32; w++) {
            int j = w * 32 + lane;
            bool sup = false;
            if (j > i && slbF[j] == li)
                sup = iou_sup(bi, ai, sobF[j], sarF[j]);
            uint bits = __ballot_sync(0xffffffffu, sup);
            if (lane == w) myword = bits;
        }
        smaskd[i * 32 + lane] = (lane >= r) ? myword : 0u;
    }
    __syncthreads();
    if (t < 32) {
        uint validw = g_validbits[n][lane];
        uint removew = 0u;
        for (int g = 0; g < 32; g++) {
            uint cur_sup = __shfl_sync(0xffffffffu, removew, g);
            uint cur_val = __shfl_sync(0xffffffffu, validw, g);
            uint rowv[32], diag[32];
#pragma unroll
            for (int b = 0; b < 32; b++) {
                rowv[b] = smaskd[(g * 32 + b) * 32 + lane];
                diag[b] = smaskd[(g * 32 + b) * 32 + g];
            }
#pragma unroll
            for (int b = 0; b < 32; b++) {
                bool alive = ((cur_val >> b) & 1u) && !((cur_sup >> b) & 1u);
                if (alive) { removew |= rowv[b]; cur_sup |= diag[b]; }
            }
        }
        uint keepw = validw & ~removew;
        int cnt = __popc(keepw);
        int inc = cnt;
        for (int o = 1; o < 32; o <<= 1) {
            int v = __shfl_up_sync(0xffffffffu, inc, o);
            if (lane >= o) inc += v;
        }
        int basei = inc - cnt;
        uint m = keepw;
        while (m) {
            int b = __ffs(m) - 1;
            m &= m - 1;
            int rank = basei + __popc(keepw & ((1u << b) - 1u));
            if (rank < 100) {
                int i = lane * 32 + b;
                float* o6 = out + ((size_t)n * 100 + rank) * 6;
                o6[0] = g_box[n][i][0]; o6[1] = g_box[n][i][1];
                o6[2] = g_box[n][i][2]; o6[3] = g_box[n][i][3];
                o6[4] = g_lab[n][i];    o6[5] = g_sc[n][i];
            }
        }
    }
    __syncthreads();
    if (t == 0) g_candcnt[n] = 0u;
}

// ---------------- launch -----------------------------------------------------
extern "C" void kernel_launch(void* const* d_in, const int* in_sizes, int n_in,
                              void* d_out, int out_size) {
    const float* loc  = (const float*)d_in[0];
    const float* cls  = (const float*)d_in[1];
    const float* reg  = (const float*)d_in[2];
    const float* ctr  = (const float*)d_in[3];
    const float* info = (const float*)d_in[4];
    float* out = (float*)d_out;
    (void)in_sizes; (void)n_in; (void)out_size;

    cudaFuncSetAttribute(k_finish, cudaFuncAttributeMaxDynamicSharedMemorySize,
                         KPAD * 32 * 4);

    k_hist<<<dim3(SBLK, NIMG), 256>>>(cls, ctr);
    k_prep<<<dim3(60, NIMG), 256>>>(ctr);
    k_compact<<<dim3(15, 20, NIMG), 256>>>(cls, ctr);
    k_finish<<<NIMG, 1024, KPAD * 32 * 4>>>(cls, ctr, loc, reg, info, out);
}